// round 13
// baseline (speedup 1.0000x reference)
#include <cuda_runtime.h>
#include <cuda_bf16.h>

// ---------------- problem constants ----------------
#define BATCH   8
#define SEQ     2048
#define DMODEL  256
#define NHEAD   8
#define DHEAD   32
#define NHID    1024
#define NLAY    4
#define NTOK    (BATCH*SEQ)        // 16384
#define LOUT    50
#define ATT_SCALE 0.17677669529663687f   // 1/sqrt(32)

// ---------------- scratch ----------------
__device__ __align__(256) float          d_X32 [NTOK*DMODEL];
__device__ __align__(256) __nv_bfloat16  d_Xb  [NTOK*DMODEL];
__device__ __align__(256) __nv_bfloat16  d_QKVb[NTOK*3*DMODEL];
__device__ __align__(256) __nv_bfloat16  d_ATTb[NTOK*DMODEL];
__device__ __align__(256) __nv_bfloat16  d_Hb  [NTOK*NHID];
__device__ __align__(256) __nv_bfloat16  d_WqkvB[NLAY*3*DMODEL*DMODEL];
__device__ __align__(256) __nv_bfloat16  d_WoB  [NLAY*DMODEL*DMODEL];
__device__ __align__(256) __nv_bfloat16  d_W1B  [NLAY*NHID*DMODEL];
__device__ __align__(256) __nv_bfloat16  d_W2B  [NLAY*DMODEL*NHID];
__device__ __align__(256) float          d_u[768];
__device__ __align__(256) float          d_c[768];

// ---------------- PTX helpers ----------------
__device__ __forceinline__ unsigned smem_u32(const void* p){
    return (unsigned)__cvta_generic_to_shared(p);
}
#define CPA(dst, src) asm volatile("cp.async.cg.shared.global [%0], [%1], 16;" :: "r"(dst), "l"(src))
#define CPC() asm volatile("cp.async.commit_group;")
#define CPW0() asm volatile("cp.async.wait_group 0;")
#define CPW1() asm volatile("cp.async.wait_group 1;")
#define LDSM4(r0,r1,r2,r3,a) asm volatile("ldmatrix.sync.aligned.m8n8.x4.shared.b16 {%0,%1,%2,%3}, [%4];" \
    : "=r"(r0),"=r"(r1),"=r"(r2),"=r"(r3) : "r"(a))
#define LDSM4T(r0,r1,r2,r3,a) asm volatile("ldmatrix.sync.aligned.m8n8.x4.trans.shared.b16 {%0,%1,%2,%3}, [%4];" \
    : "=r"(r0),"=r"(r1),"=r"(r2),"=r"(r3) : "r"(a))
#define MMA16816(d0,d1,d2,d3, a0,a1,a2,a3, b0,b1) \
    asm volatile("mma.sync.aligned.m16n8k16.row.col.f32.bf16.bf16.f32 " \
        "{%0,%1,%2,%3}, {%4,%5,%6,%7}, {%8,%9}, {%0,%1,%2,%3};" \
        : "+f"(d0),"+f"(d1),"+f"(d2),"+f"(d3) \
        : "r"(a0),"r"(a1),"r"(a2),"r"(a3), "r"(b0),"r"(b1))

__device__ __forceinline__ unsigned pkbf2(float lo, float hi){
    unsigned d;
    asm("cvt.rn.bf16x2.f32 %0, %1, %2;" : "=r"(d) : "f"(hi), "f"(lo));
    return d;
}
__device__ __forceinline__ unsigned prmt_hi(unsigned a, unsigned b){
    unsigned d;
    asm("prmt.b32 %0, %1, %2, 0x7632;" : "=r"(d) : "r"(a), "r"(b));
    return d;
}
#define EXP_B0 1064986316.0f
#define EXP_SA (12102203.161f * ATT_SCALE)
__device__ __forceinline__ float cexpb(float s, float base){
    float t = fmaf(s, EXP_SA, base);
    t = fmaxf(t, 0.f);
    return __int_as_float((int)t);
}

// ---------------- merged weight conversion ----------------
#define N0 (NLAY*768*256)
#define N1 (NLAY*256*256)
#define N2 (NLAY*NHID*256)
#define N3 (NLAY*256*NHID)
__global__ void conv4_kernel(const float* __restrict__ s0, const float* __restrict__ s1,
                             const float* __restrict__ s2, const float* __restrict__ s3)
{
    int i = (blockIdx.x*blockDim.x + threadIdx.x)*4;
    const float* s; __nv_bfloat16* d;
    if      (i < N0)         { s = s0 + i;              d = d_WqkvB + i; }
    else if (i < N0+N1)      { s = s1 + (i-N0);         d = d_WoB  + (i-N0); }
    else if (i < N0+N1+N2)   { s = s2 + (i-N0-N1);      d = d_W1B  + (i-N0-N1); }
    else                     { s = s3 + (i-N0-N1-N2);   d = d_W2B  + (i-N0-N1-N2); }
    float4 v = *(const float4*)s;
    uint2 o; o.x = pkbf2(v.x, v.y); o.y = pkbf2(v.z, v.w);
    *(uint2*)d = o;
}

// ---------------- rank-1 layer-0 QKV precompute ----------------
__global__ void prep0_kernel(const float* __restrict__ Wqkv, const float* __restrict__ bqkv,
                             const float* __restrict__ W_emb, const float* __restrict__ b_emb)
{
    int wid = threadIdx.x >> 5, lane = threadIdx.x & 31;
    for (int j = wid; j < 768; j += 8){
        const float* row = Wqkv + (size_t)j*256;
        float su = 0.f, sc = 0.f;
        #pragma unroll
        for (int i=0;i<8;i++){
            float w = row[lane + i*32];
            su = fmaf(w, W_emb[lane + i*32], su);
            sc = fmaf(w, b_emb[lane + i*32], sc);
        }
        #pragma unroll
        for (int o=16;o>0;o>>=1){
            su += __shfl_xor_sync(0xffffffffu, su, o);
            sc += __shfl_xor_sync(0xffffffffu, sc, o);
        }
        if (lane == 0){ d_u[j] = su; d_c[j] = sc + bqkv[j]; }
    }
}

// ---------------- embed + layer-0 QKV (rank-1) ----------------
__global__ void embed0_kernel(const float* __restrict__ inputs,
                              const float* __restrict__ W_emb,
                              const float* __restrict__ b_emb)
{
    int tok = blockIdx.x;
    int d   = threadIdx.x;
    float y = __ldg(&inputs[(size_t)tok*4]);
    float v = fmaf(y, W_emb[d], b_emb[d]);
    d_X32[(size_t)tok*DMODEL + d] = v;
    #pragma unroll
    for (int t=0;t<3;t++){
        int j = d + t*256;
        float q = fmaf(y, d_u[j], d_c[j]);
        d_QKVb[(size_t)tok*768 + j] = __float2bfloat16(q);
    }
}

// ---------------- bf16 GEMM: 128x128 tile, BK=64, 3-stage, 1 sync/iter ----------------
#define G_STG (128*72)
#define GEMM_SMEM 110592
__global__ __launch_bounds__(256) void gemm_kernel(
    const __nv_bfloat16* __restrict__ A,
    const __nv_bfloat16* __restrict__ B,
    const float* __restrict__ bias,
    __nv_bfloat16* __restrict__ outB,
    int N, int K, int relu, int mStride, int mOff, int n0Add)
{
    extern __shared__ __align__(16) unsigned char dynsm[];
    __nv_bfloat16* As = (__nv_bfloat16*)dynsm;       // [3][128*72]
    __nv_bfloat16* Bs = As + 3*G_STG;                // [3][128*72]

    const int tid = threadIdx.x;
    const int wid = tid >> 5, lane = tid & 31;
    const int wm  = wid >> 1, wn = wid & 1;
    const int r8 = lane & 7, sel = lane >> 3;
    const int m0  = (blockIdx.y * mStride + mOff) * 128;
    const int n0  = blockIdx.x * 128 + n0Add;

    float c[2][8][4];
    #pragma unroll
    for (int x=0;x<2;x++)
        #pragma unroll
        for (int j=0;j<8;j++){ c[x][j][0]=0.f;c[x][j][1]=0.f;c[x][j][2]=0.f;c[x][j][3]=0.f; }

    const int kIter = K >> 6;

    auto issue = [&](int i, int bf){
        const __nv_bfloat16* Ag = A + (size_t)m0*K + i*64;
        const __nv_bfloat16* Bg = B + (size_t)n0*K + i*64;
        __nv_bfloat16* Ad = As + bf*G_STG;
        __nv_bfloat16* Bd = Bs + bf*G_STG;
        #pragma unroll
        for (int cc = tid; cc < 1024; cc += 256){
            int r = cc >> 3, off = (cc & 7)*8;
            CPA(smem_u32(&Ad[r*72+off]), Ag + (size_t)r*K + off);
            CPA(smem_u32(&Bd[r*72+off]), Bg + (size_t)r*K + off);
        }
    };

    issue(0, 0); CPC();
    if (kIter > 1){ issue(1, 1); CPC(); }

    int cur = 0;
    for (int i = 0; i < kIter; i++){
        if (i+1 < kIter) CPW1(); else CPW0();
        __syncthreads();
        if (i+2 < kIter){
            int st = cur+2; if (st>=3) st-=3;
            issue(i+2, st); CPC();
        }
        const __nv_bfloat16* Asb = As + cur*G_STG;
        const __nv_bfloat16* Bsb = Bs + cur*G_STG;

        #pragma unroll
        for (int half = 0; half < 2; half++){
            unsigned a[2][2][4];
            #pragma unroll
            for (int x=0;x<2;x++)
                #pragma unroll
                for (int t=0;t<2;t++){
                    int row = wm*32 + x*16 + (sel&1)*8 + r8;
                    unsigned addr = smem_u32(&Asb[row*72 + half*32 + t*16 + (sel>>1)*8]);
                    LDSM4(a[x][t][0], a[x][t][1], a[x][t][2], a[x][t][3], addr);
                }
            #pragma unroll
            for (int j=0;j<8;j++){
                unsigned b0,b1,b2,b3;
                unsigned addr = smem_u32(&Bsb[(wn*64 + j*8 + r8)*72 + half*32 + sel*8]);
                LDSM4(b0,b1,b2,b3, addr);
                #pragma unroll
                for (int x=0;x<2;x++){
                    MMA16816(c[x][j][0],c[x][j][1],c[x][j][2],c[x][j][3],
                             a[x][0][0],a[x][0][1],a[x][0][2],a[x][0][3], b0,b1);
                    MMA16816(c[x][j][0],c[x][j][1],c[x][j][2],c[x][j][3],
                             a[x][1][0],a[x][1][1],a[x][1][2],a[x][1][3], b2,b3);
                }
            }
        }
        cur = (cur+1 == 3) ? 0 : cur+1;
    }

    // register-direct epilogue (no smem, no sync)
    const int g = lane >> 2, tg = lane & 3;
    #pragma unroll
    for (int x=0;x<2;x++){
        int row0 = m0 + wm*32 + x*16 + g;
        #pragma unroll
        for (int j=0;j<8;j++){
            int col = n0 + wn*64 + j*8 + 2*tg;
            float b0 = bias[col], b1 = bias[col+1];
            float v00 = c[x][j][0] + b0, v01 = c[x][j][1] + b1;
            float v10 = c[x][j][2] + b0, v11 = c[x][j][3] + b1;
            if (relu){
                v00 = fmaxf(v00,0.f); v01 = fmaxf(v01,0.f);
                v10 = fmaxf(v10,0.f); v11 = fmaxf(v11,0.f);
            }
            *(unsigned*)&outB[(size_t)row0*N + col]     = pkbf2(v00, v01);
            *(unsigned*)&outB[(size_t)(row0+8)*N + col] = pkbf2(v10, v11);
        }
    }
}

// ---------------- GEMM + bias + resid + LN fused: 64x256 tile, BK=32, 3-stage ----------------
#define GL_ASTG (64*40)
#define GL_BSTG (256*40)
#define GL_STG  (GL_ASTG + GL_BSTG)
__global__ __launch_bounds__(256) void gemm_ln_kernel(
    const __nv_bfloat16* __restrict__ A,
    const __nv_bfloat16* __restrict__ B,
    const float* __restrict__ bias,
    const float* __restrict__ g,
    const float* __restrict__ bta,
    int K, int sparse)
{
    extern __shared__ __align__(16) unsigned char dynsm[];
    __nv_bfloat16* St = (__nv_bfloat16*)dynsm;       // [3][A 64*40 | B 256*40]
    float*         Cs = (float*)dynsm;               // [32][264] epilogue alias

    const int tid = threadIdx.x;
    const int wid = tid >> 5, lane = tid & 31;
    const int wm  = wid >> 2, wn = wid & 3;
    const int r8 = lane & 7, sel = lane >> 3;
    const int t64 = sparse ? ((blockIdx.y >> 1)*32 + 30 + (blockIdx.y & 1)) : blockIdx.y;
    const int m0  = t64 * 64;

    float c[2][8][4];
    #pragma unroll
    for (int x=0;x<2;x++)
        #pragma unroll
        for (int j=0;j<8;j++){ c[x][j][0]=0.f;c[x][j][1]=0.f;c[x][j][2]=0.f;c[x][j][3]=0.f; }

    const int kIter = K >> 5;

    auto issue = [&](int i, int bf){
        const __nv_bfloat16* Ag = A + (size_t)m0*K + i*32;
        const __nv_bfloat16* Bg = B + i*32;
        __nv_bfloat16* Ad = St + bf*GL_STG;
        __nv_bfloat16* Bd = Ad + GL_ASTG;
        {
            int r = tid >> 2, off = (tid & 3)*8;
            CPA(smem_u32(&Ad[r*40+off]), Ag + (size_t)r*K + off);
        }
        #pragma unroll
        for (int cc = tid; cc < 1024; cc += 256){
            int r = cc >> 2, off = (cc & 3)*8;
            CPA(smem_u32(&Bd[r*40+off]), Bg + (size_t)r*K + off);
        }
    };

    issue(0, 0); CPC();
    if (kIter > 1){ issue(1, 1); CPC(); }

    int cur = 0;
    for (int i = 0; i < kIter; i++){
        if (i+1 < kIter) CPW1(); else CPW0();
        __syncthreads();
        if (i+2 < kIter){
            int st = cur+2; if (st>=3) st-=3;
            issue(i+2, st); CPC();
        }
        const __nv_bfloat16* Asb = St + cur*GL_STG;
        const __nv_bfloat16* Bsb = Asb + GL_ASTG;

        unsigned a[2][2][4];
        #pragma unroll
        for (int x=0;x<2;x++)
            #pragma unroll
            for (int t=0;t<2;t++){
                int row = wm*32 + x*16 + (sel&1)*8 + r8;
                unsigned addr = smem_u32(&Asb[row*40 + t*16 + (sel>>1)*8]);
                LDSM4(a[x][t][0], a[x][t][1], a[x][t][2], a[x][t][3], addr);
            }
        #pragma unroll
        for (int j=0;j<8;j++){
            unsigned b0,b1,b2,b3;
            unsigned addr = smem_u32(&Bsb[(wn*64 + j*8 + r8)*40 + sel*8]);
            LDSM4(b0,b1,b2,b3, addr);
            #pragma unroll
            for (int x=0;x<2;x++){
                MMA16816(c[x][j][0],c[x][j][1],c[x][j][2],c[x][j][3],
                         a[x][0][0],a[x][0][1],a[x][0][2],a[x][0][3], b0,b1);
                MMA16816(c[x][j][0],c[x][j][1],c[x][j][2],c[x][j][3],
                         a[x][1][0],a[x][1][1],a[x][1][2],a[x][1][3], b2,b3);
            }
        }
        cur = (cur+1 == 3) ? 0 : cur+1;
    }
    __syncthreads();   // all compute done before Cs aliases stage smem

    const int gq = lane >> 2, tg = lane & 3;
    #pragma unroll
    for (int chunk = 0; chunk < 2; chunk++){
        if (wm == chunk){
            #pragma unroll
            for (int x=0;x<2;x++){
                #pragma unroll
                for (int j=0;j<8;j++){
                    int colL = wn*64 + j*8 + 2*tg;
                    *(float2*)&Cs[(x*16 + gq)*264 + colL]     = make_float2(c[x][j][0], c[x][j][1]);
                    *(float2*)&Cs[(x*16 + gq + 8)*264 + colL] = make_float2(c[x][j][2], c[x][j][3]);
                }
            }
        }
        __syncthreads();
        #pragma unroll
        for (int ii=0; ii<4; ii++){
            int rloc = wid*4 + ii;
            int tok  = m0 + chunk*32 + rloc;
            float v[8]; float s = 0.f;
            #pragma unroll
            for (int i2=0;i2<4;i2++){
                int c0 = 2*lane + 64*i2;
                v[2*i2]   = Cs[rloc*264 + c0]   + bias[c0]   + d_X32[(size_t)tok*DMODEL + c0];
                v[2*i2+1] = Cs[rloc*264 + c0+1] + bias[c0+1] + d_X32[(size_t)tok*DMODEL + c0+1];
                s += v[2*i2] + v[2*i2+1];
            }
            #pragma unroll
            for (int o=16;o>0;o>>=1) s += __shfl_xor_sync(0xffffffffu, s, o);
            float mean = s * (1.f/256.f);
            float q = 0.f;
            #pragma unroll
            for (int i2=0;i2<8;i2++){ float dd = v[i2]-mean; q = fmaf(dd, dd, q); }
            #pragma unroll
            for (int o=16;o>0;o>>=1) q += __shfl_xor_sync(0xffffffffu, q, o);
            float rstd = rsqrtf(q*(1.f/256.f) + 1e-5f);
            #pragma unroll
            for (int i2=0;i2<4;i2++){
                int c0 = 2*lane + 64*i2;
                float o0 = (v[2*i2]  -mean)*rstd*g[c0]   + bta[c0];
                float o1 = (v[2*i2+1]-mean)*rstd*g[c0+1] + bta[c0+1];
                *(float2*)&d_X32[(size_t)tok*DMODEL + c0] = make_float2(o0, o1);
                *(unsigned*)&d_Xb[(size_t)tok*DMODEL + c0] = pkbf2(o0, o1);
            }
        }
        __syncthreads();
    }
}

// ---------------- flash attention: 128 q rows, 3-stage K/V, MMA-based row sums ----------------
#define A_STG (128*40)
#define ONEB 0x3F803F80u      // bf16(1.0) x2
__global__ __launch_bounds__(256, 3) void attn_kernel(int qtBase, int useMax)
{
    extern __shared__ __align__(16) unsigned char dynsm_a[];
    __nv_bfloat16* Qs = (__nv_bfloat16*)dynsm_a;     // 128*40
    __nv_bfloat16* Ks = Qs + A_STG;                  // [3][128*40]
    __nv_bfloat16* Vs = Ks + 3*A_STG;                // [3][128*40]

    const int tid = threadIdx.x, lane = tid & 31, w = tid >> 5;
    const int qt = qtBase - blockIdx.x;              // heavy tiles first
    const int bh = blockIdx.y, b = bh >> 3, h = bh & 7;
    const int g = lane >> 2, tig = lane & 3;
    const int r8 = lane & 7, sel = lane >> 3;
    const int rwBase = qt*128 + w*16;

    auto issueKV = [&](int kt, int st){
        const __nv_bfloat16* Kg = d_QKVb + ((size_t)(b*SEQ + kt*128))*768 + 256 + h*32;
        #pragma unroll
        for (int cc = tid; cc < 512; cc += 256){
            int r = cc >> 2, off = (cc & 3)*8;
            CPA(smem_u32(&Ks[st*A_STG + r*40+off]), Kg + (size_t)r*768 + off);
            CPA(smem_u32(&Vs[st*A_STG + r*40+off]), Kg + 256 + (size_t)r*768 + off);
        }
    };

    {
        const __nv_bfloat16* Qg = d_QKVb + ((size_t)(b*SEQ + qt*128))*768 + h*32;
        #pragma unroll
        for (int cc = tid; cc < 512; cc += 256){
            int r = cc >> 2, off = (cc & 3)*8;
            CPA(smem_u32(&Qs[r*40+off]), Qg + (size_t)r*768 + off);
        }
        issueKV(0, 0); CPC();
        if (qt >= 1){ issueKV(1, 1); CPC(); }
    }

    unsigned aq[2][4];
    float o[4][4];
    #pragma unroll
    for (int j=0;j<4;j++){ o[j][0]=0.f;o[j][1]=0.f;o[j][2]=0.f;o[j][3]=0.f; }
    float ls[4] = {0.f, 0.f, 0.f, 0.f};   // MMA row-sum accumulator (P @ ones)
    float m0v = -1e30f, m1v = -1e30f;
    const int gr0 = rwBase + g;

    int cur = 0;
    for (int kt = 0; kt <= qt; kt++){
        if (kt < qt) CPW1(); else CPW0();
        __syncthreads();
        if (kt == 0){
            int row = w*16 + (sel & 1)*8 + r8;
            #pragma unroll
            for (int t=0;t<2;t++){
                unsigned addr = smem_u32(&Qs[row*40 + t*16 + (sel>>1)*8]);
                LDSM4(aq[t][0], aq[t][1], aq[t][2], aq[t][3], addr);
            }
        }
        if (kt+2 <= qt){
            int st = cur+2; if (st>=3) st-=3;
            issueKV(kt+2, st); CPC();
        }

        const __nv_bfloat16* Kb = Ks + cur*A_STG;
        const __nv_bfloat16* Vb = Vs + cur*A_STG;

        #pragma unroll
        for (int h2 = 0; h2 < 2; h2++){
            const int cb = kt*128 + h2*64;
            if (cb > rwBase + 15) break;

            float s[8][4];
            #pragma unroll
            for (int j=0;j<8;j++){
                s[j][0]=0.f;s[j][1]=0.f;s[j][2]=0.f;s[j][3]=0.f;
                unsigned k0,k1,k2,k3;
                unsigned addr = smem_u32(&Kb[(h2*64 + j*8 + r8)*40 + sel*8]);
                LDSM4(k0,k1,k2,k3, addr);
                MMA16816(s[j][0],s[j][1],s[j][2],s[j][3],
                         aq[0][0],aq[0][1],aq[0][2],aq[0][3], k0,k1);
                MMA16816(s[j][0],s[j][1],s[j][2],s[j][3],
                         aq[1][0],aq[1][1],aq[1][2],aq[1][3], k2,k3);
            }

            const bool diag = (cb + 63 > rwBase);
            if (diag){
                #pragma unroll
                for (int j=0;j<8;j++){
                    int c0 = cb + j*8 + 2*tig;
                    if (c0   > gr0)   s[j][0] = -1e30f;
                    if (c0+1 > gr0)   s[j][1] = -1e30f;
                    if (c0   > gr0+8) s[j][2] = -1e30f;
                    if (c0+1 > gr0+8) s[j][3] = -1e30f;
                }
            }

            float base0 = EXP_B0, base1 = EXP_B0;
            if (useMax){
                float mt0 = -1e30f, mt1 = -1e30f;
                #pragma unroll
                for (int j=0;j<8;j++){
                    mt0 = fmaxf(mt0, fmaxf(s[j][0], s[j][1]));
                    mt1 = fmaxf(mt1, fmaxf(s[j][2], s[j][3]));
                }
                mt0 = fmaxf(mt0, __shfl_xor_sync(0xffffffffu, mt0, 1));
                mt0 = fmaxf(mt0, __shfl_xor_sync(0xffffffffu, mt0, 2));
                mt1 = fmaxf(mt1, __shfl_xor_sync(0xffffffffu, mt1, 1));
                mt1 = fmaxf(mt1, __shfl_xor_sync(0xffffffffu, mt1, 2));
                float nm0 = fmaxf(m0v, mt0), nm1 = fmaxf(m1v, mt1);
                base0 = EXP_B0 - EXP_SA*nm0;
                base1 = EXP_B0 - EXP_SA*nm1;
                float corr0 = cexpb(m0v, base0), corr1 = cexpb(m1v, base1);
                m0v = nm0; m1v = nm1;
                ls[0] *= corr0; ls[1] *= corr0;
                ls[2] *= corr1; ls[3] *= corr1;
                #pragma unroll
                for (int j=0;j<4;j++){
                    o[j][0] *= corr0; o[j][1] *= corr0;
                    o[j][2] *= corr1; o[j][3] *= corr1;
                }
            }

            const bool clampP = useMax || diag;
            unsigned pp[4][4];
            #pragma unroll
            for (int t=0;t<4;t++){
                float t00 = fmaf(s[2*t][0],   EXP_SA, base0), t01 = fmaf(s[2*t][1],   EXP_SA, base0);
                float t02 = fmaf(s[2*t][2],   EXP_SA, base1), t03 = fmaf(s[2*t][3],   EXP_SA, base1);
                float t10 = fmaf(s[2*t+1][0], EXP_SA, base0), t11 = fmaf(s[2*t+1][1], EXP_SA, base0);
                float t12 = fmaf(s[2*t+1][2], EXP_SA, base1), t13 = fmaf(s[2*t+1][3], EXP_SA, base1);
                if (clampP){
                    t00 = fmaxf(t00,0.f); t01 = fmaxf(t01,0.f);
                    t02 = fmaxf(t02,0.f); t03 = fmaxf(t03,0.f);
                    t10 = fmaxf(t10,0.f); t11 = fmaxf(t11,0.f);
                    t12 = fmaxf(t12,0.f); t13 = fmaxf(t13,0.f);
                }
                int i00 = (int)t00, i01 = (int)t01, i02 = (int)t02, i03 = (int)t03;
                int i10 = (int)t10, i11 = (int)t11, i12 = (int)t12, i13 = (int)t13;
                pp[t][0] = prmt_hi((unsigned)i00, (unsigned)i01);
                pp[t][1] = prmt_hi((unsigned)i02, (unsigned)i03);
                pp[t][2] = prmt_hi((unsigned)i10, (unsigned)i11);
                pp[t][3] = prmt_hi((unsigned)i12, (unsigned)i13);
            }

            #pragma unroll
            for (int t=0;t<4;t++){
                unsigned v0,v1,v2,v3, x0,x1,x2,x3;
                int vrow = h2*64 + 16*t + (sel & 1)*8 + r8;
                unsigned addrA = smem_u32(&Vb[vrow*40 + (sel>>1)*8]);
                unsigned addrB = smem_u32(&Vb[vrow*40 + 16 + (sel>>1)*8]);
                LDSM4T(v0,v1,v2,v3, addrA);
                LDSM4T(x0,x1,x2,x3, addrB);
                MMA16816(o[0][0],o[0][1],o[0][2],o[0][3], pp[t][0],pp[t][1],pp[t][2],pp[t][3], v0,v1);
                MMA16816(o[1][0],o[1][1],o[1][2],o[1][3], pp[t][0],pp[t][1],pp[t][2],pp[t][3], v2,v3);
                MMA16816(o[2][0],o[2][1],o[2][2],o[2][3], pp[t][0],pp[t][1],pp[t][2],pp[t][3], x0,x1);
                MMA16816(o[3][0],o[3][1],o[3][2],o[3][3], pp[t][0],pp[t][1],pp[t][2],pp[t][3], x2,x3);
                // row-sum tile: P @ ones (every column of this n8 tile = row sum)
                MMA16816(ls[0],ls[1],ls[2],ls[3],
                         pp[t][0],pp[t][1],pp[t][2],pp[t][3], ONEB, ONEB);
            }
        }
        cur = (cur+1 == 3) ? 0 : cur+1;
    }

    // ls[0] = row-sum for row g, ls[2] = row-sum for row g+8 (no shuffles needed)
    float rl0 = __fdividef(1.f, ls[0]), rl1 = __fdividef(1.f, ls[2]);
    __nv_bfloat16* Og0 = d_ATTb + ((size_t)(b*SEQ + rwBase + g))*256 + h*32;
    __nv_bfloat16* Og1 = Og0 + (size_t)8*256;
    #pragma unroll
    for (int j=0;j<4;j++){
        int dcol = j*8 + 2*tig;
        *(unsigned*)&Og0[dcol] = pkbf2(o[j][0]*rl0, o[j][1]*rl0);
        *(unsigned*)&Og1[dcol] = pkbf2(o[j][2]*rl1, o[j][3]*rl1);
    }
}

// ---------------- dec + hist + IDM + fusion ----------------
__global__ void final_kernel(const float* __restrict__ inputs,
    const float* __restrict__ his,
    const float* __restrict__ W_dec, const float* __restrict__ b_dec,
    const float* __restrict__ W_fus, const float* __restrict__ b_fus,
    float* __restrict__ out)
{
    __shared__ float dec[8], yidm[8][LOUT], lastpos[8], dvb[8];
    int tid = threadIdx.x, wid = tid>>5, lane = tid&31;
    {
        const float* row = d_X32 + ((size_t)(wid*SEQ + SEQ-1))*DMODEL;
        float s = 0.f;
        #pragma unroll
        for (int i=0;i<8;i++){ int d_ = lane + i*32; s += row[d_]*W_dec[d_]; }
        #pragma unroll
        for (int o=16;o>0;o>>=1) s += __shfl_xor_sync(0xffffffffu, s, o);
        if (lane==0) dec[wid] = s + b_dec[0];
    }
    if (tid < 8){
        int b = tid;
        float lp = inputs[((size_t)(b*SEQ + SEQ-1))*4];
        lastpos[b] = lp;
        dvb[b] = (lp - inputs[((size_t)(b*SEQ + SEQ-1-LOUT))*4]) / 50.f;
    }
    __syncthreads();

    if (tid < 8){
        int b = tid;
        const float* il = inputs + ((size_t)(b*SEQ + SEQ-1))*4;
        float y = il[0], v = il[1], sg = il[2], dv = il[3];
        const float sqab2 = 2.449489742783178f;
        float sx = 2.0f + fmaxf(0.f, v*1.5f + v*dv/sqab2);
        float t = v/30.0f; float p = t*t; p *= p;
        float rr = sx/sg;
        float af = (1.f - p - rr*rr);
        float v0 = fmaxf(v + af*0.1f, 0.f);
        float v0last = __shfl_sync(0xffu, v0, 7);   // reference's v0[-1] broadcast
        float yp = y + v0last*0.1f;
        float vp = v0;
        yidm[b][0] = yp;
        for (int j=0;j<LOUT-1;j++){
            float hp = his[((size_t)(b*LOUT + j))*2];
            float hv = his[((size_t)(b*LOUT + j))*2 + 1];
            float dvj = hv - vp;
            float sj  = hp - yp;
            float sxj = 2.0f + fmaxf(0.f, vp*1.5f + vp*dvj/sqab2);
            float tt = vp/30.0f; float q4 = tt*tt; q4 *= q4;
            float r2 = sxj/sj;
            float acc = (1.f - q4 - r2*r2);
            float v2 = vp + acc*0.1f;
            v2 = (v2 <= 0.f) ? 0.f : v2;
            yp = yp + v2*0.1f;
            yidm[b][j+1] = yp;
            vp = v2;
        }
    }
    __syncthreads();

    float w0 = W_fus[0], w1 = W_fus[1], w2 = W_fus[2], bb = b_fus[0];
    for (int t = tid; t < BATCH*LOUT; t += 256){
        int b = t / LOUT, l = t % LOUT;
        out[t] = w0*dec[b] + w1*(lastpos[b] + dvb[b]*(float)(l+1)) + w2*yidm[b][l] + bb;
    }
}

// ---------------- launcher ----------------
#define GLN_SMEM    76800
#define ATT_SMEM    71680

extern "C" void kernel_launch(void* const* d_in, const int* in_sizes, int n_in,
                              void* d_out, int out_size)
{
    (void)in_sizes; (void)n_in; (void)out_size;
    const float* inputs = (const float*)d_in[0];
    const float* his    = (const float*)d_in[1];
    const float* W_emb  = (const float*)d_in[2];
    const float* b_emb  = (const float*)d_in[3];
    const float* Wqkv   = (const float*)d_in[4];
    const float* bqkv   = (const float*)d_in[5];
    const float* Wo     = (const float*)d_in[6];
    const float* bo     = (const float*)d_in[7];
    const float* W1     = (const float*)d_in[8];
    const float* b1     = (const float*)d_in[9];
    const float* W2     = (const float*)d_in[10];
    const float* b2     = (const float*)d_in[11];
    const float* ln1g   = (const float*)d_in[12];
    const float* ln1b   = (const float*)d_in[13];
    const float* ln2g   = (const float*)d_in[14];
    const float* ln2b   = (const float*)d_in[15];
    const float* W_dec  = (const float*)d_in[16];
    const float* b_dec  = (const float*)d_in[17];
    const float* W_fus  = (const float*)d_in[18];
    const float* b_fus  = (const float*)d_in[19];
    float* out = (float*)d_out;

    cudaFuncSetAttribute(gemm_kernel,    cudaFuncAttributeMaxDynamicSharedMemorySize, GEMM_SMEM);
    cudaFuncSetAttribute(gemm_ln_kernel, cudaFuncAttributeMaxDynamicSharedMemorySize, GLN_SMEM);
    cudaFuncSetAttribute(attn_kernel,    cudaFuncAttributeMaxDynamicSharedMemorySize, ATT_SMEM);

    void *pXb_, *pHb_, *pWq_, *pWo_, *pW1_, *pW2_, *pATT_, *pQKV_;
    cudaGetSymbolAddress(&pXb_,  d_Xb);
    cudaGetSymbolAddress(&pHb_,  d_Hb);
    cudaGetSymbolAddress(&pWq_,  d_WqkvB);
    cudaGetSymbolAddress(&pWo_,  d_WoB);
    cudaGetSymbolAddress(&pW1_,  d_W1B);
    cudaGetSymbolAddress(&pW2_,  d_W2B);
    cudaGetSymbolAddress(&pATT_, d_ATTb);
    cudaGetSymbolAddress(&pQKV_, d_QKVb);

    __nv_bfloat16* Xb   = (__nv_bfloat16*)pXb_;
    __nv_bfloat16* Hb   = (__nv_bfloat16*)pHb_;
    __nv_bfloat16* WqB  = (__nv_bfloat16*)pWq_;
    __nv_bfloat16* WoB  = (__nv_bfloat16*)pWo_;
    __nv_bfloat16* W1B  = (__nv_bfloat16*)pW1_;
    __nv_bfloat16* W2B  = (__nv_bfloat16*)pW2_;
    __nv_bfloat16* ATTb = (__nv_bfloat16*)pATT_;
    __nv_bfloat16* QKVb = (__nv_bfloat16*)pQKV_;

    conv4_kernel<<<(N0+N1+N2+N3)/4/256, 256>>>(Wqkv, Wo, W1, W2);
    prep0_kernel<<<1, 256>>>(Wqkv, bqkv, W_emb, b_emb);
    embed0_kernel<<<NTOK, 256>>>(inputs, W_emb, b_emb);

    for (int l = 0; l < NLAY; l++){
        int sp = (l == NLAY-1);
        int useMax = (l == 0);

        if (l > 0){
            if (!sp){
                gemm_kernel<<<dim3(6,128), 256, GEMM_SMEM>>>(Xb, WqB + (size_t)l*768*256,
                    bqkv + l*768, QKVb, 768, 256, 0, 1, 0, 0);
            } else {
                gemm_kernel<<<dim3(4,128), 256, GEMM_SMEM>>>(Xb, WqB + (size_t)l*768*256,
                    bqkv + l*768, QKVb, 768, 256, 0, 1, 0, 256);
                gemm_kernel<<<dim3(2,8), 256, GEMM_SMEM>>>(Xb, WqB + (size_t)l*768*256,
                    bqkv + l*768, QKVb, 768, 256, 0, 16, 15, 0);
            }
        }

        if (!sp) attn_kernel<<<dim3(16,64), 256, ATT_SMEM>>>(15, useMax);
        else     attn_kernel<<<dim3(1,64),  256, ATT_SMEM>>>(15, useMax);

        gemm_ln_kernel<<<dim3(1, sp?16:256), 256, GLN_SMEM>>>(ATTb, WoB + (size_t)l*256*256,
            bo + l*256, ln1g + l*256, ln1b + l*256, 256, sp);

        gemm_kernel<<<dim3(8, sp?8:128), 256, GEMM_SMEM>>>(Xb, W1B + (size_t)l*1024*256,
            b1 + l*1024, Hb, 1024, 256, 1, sp?16:1, sp?15:0, 0);

        gemm_ln_kernel<<<dim3(1, sp?16:256), 256, GLN_SMEM>>>(Hb, W2B + (size_t)l*256*1024,
            b2 + l*256, ln2g + l*256, ln2b + l*256, 1024, sp);
    }

    final_kernel<<<1, 256>>>(inputs, his, W_dec, b_dec, W_fus, b_fus, out);
}

// round 14
// speedup vs baseline: 1.0379x; 1.0379x over previous
#include <cuda_runtime.h>
#include <cuda_bf16.h>

// ---------------- problem constants ----------------
#define BATCH   8
#define SEQ     2048
#define DMODEL  256
#define NHEAD   8
#define DHEAD   32
#define NHID    1024
#define NLAY    4
#define NTOK    (BATCH*SEQ)        // 16384
#define LOUT    50
#define ATT_SCALE 0.17677669529663687f   // 1/sqrt(32)

// ---------------- scratch ----------------
__device__ __align__(256) __nv_bfloat16  d_Xb  [NTOK*DMODEL];   // activations+residual (bf16 only)
__device__ __align__(256) __nv_bfloat16  d_QKVb[NTOK*3*DMODEL];
__device__ __align__(256) __nv_bfloat16  d_ATTb[NTOK*DMODEL];
__device__ __align__(256) __nv_bfloat16  d_Hb  [NTOK*NHID];
__device__ __align__(256) __nv_bfloat16  d_WqkvB[NLAY*3*DMODEL*DMODEL];
__device__ __align__(256) __nv_bfloat16  d_WoB  [NLAY*DMODEL*DMODEL];
__device__ __align__(256) __nv_bfloat16  d_W1B  [NLAY*NHID*DMODEL];
__device__ __align__(256) __nv_bfloat16  d_W2B  [NLAY*DMODEL*NHID];
__device__ __align__(256) float          d_u[768];
__device__ __align__(256) float          d_c[768];

// ---------------- PTX helpers ----------------
__device__ __forceinline__ unsigned smem_u32(const void* p){
    return (unsigned)__cvta_generic_to_shared(p);
}
#define CPA(dst, src) asm volatile("cp.async.cg.shared.global [%0], [%1], 16;" :: "r"(dst), "l"(src))
#define CPC() asm volatile("cp.async.commit_group;")
#define CPW0() asm volatile("cp.async.wait_group 0;")
#define CPW1() asm volatile("cp.async.wait_group 1;")
#define LDSM4(r0,r1,r2,r3,a) asm volatile("ldmatrix.sync.aligned.m8n8.x4.shared.b16 {%0,%1,%2,%3}, [%4];" \
    : "=r"(r0),"=r"(r1),"=r"(r2),"=r"(r3) : "r"(a))
#define LDSM4T(r0,r1,r2,r3,a) asm volatile("ldmatrix.sync.aligned.m8n8.x4.trans.shared.b16 {%0,%1,%2,%3}, [%4];" \
    : "=r"(r0),"=r"(r1),"=r"(r2),"=r"(r3) : "r"(a))
#define MMA16816(d0,d1,d2,d3, a0,a1,a2,a3, b0,b1) \
    asm volatile("mma.sync.aligned.m16n8k16.row.col.f32.bf16.bf16.f32 " \
        "{%0,%1,%2,%3}, {%4,%5,%6,%7}, {%8,%9}, {%0,%1,%2,%3};" \
        : "+f"(d0),"+f"(d1),"+f"(d2),"+f"(d3) \
        : "r"(a0),"r"(a1),"r"(a2),"r"(a3), "r"(b0),"r"(b1))

__device__ __forceinline__ unsigned pkbf2(float lo, float hi){
    unsigned d;
    asm("cvt.rn.bf16x2.f32 %0, %1, %2;" : "=r"(d) : "f"(hi), "f"(lo));
    return d;
}
__device__ __forceinline__ unsigned prmt_hi(unsigned a, unsigned b){
    unsigned d;
    asm("prmt.b32 %0, %1, %2, 0x7632;" : "=r"(d) : "r"(a), "r"(b));
    return d;
}
#define EXP_B0 1064986316.0f
#define EXP_SA (12102203.161f * ATT_SCALE)
__device__ __forceinline__ float cexpb(float s, float base){
    float t = fmaf(s, EXP_SA, base);
    t = fmaxf(t, 0.f);
    return __int_as_float((int)t);
}

// ---------------- merged weight conversion ----------------
#define N0 (NLAY*768*256)
#define N1 (NLAY*256*256)
#define N2 (NLAY*NHID*256)
#define N3 (NLAY*256*NHID)
__global__ void conv4_kernel(const float* __restrict__ s0, const float* __restrict__ s1,
                             const float* __restrict__ s2, const float* __restrict__ s3)
{
    int i = (blockIdx.x*blockDim.x + threadIdx.x)*4;
    const float* s; __nv_bfloat16* d;
    if      (i < N0)         { s = s0 + i;              d = d_WqkvB + i; }
    else if (i < N0+N1)      { s = s1 + (i-N0);         d = d_WoB  + (i-N0); }
    else if (i < N0+N1+N2)   { s = s2 + (i-N0-N1);      d = d_W1B  + (i-N0-N1); }
    else                     { s = s3 + (i-N0-N1-N2);   d = d_W2B  + (i-N0-N1-N2); }
    float4 v = *(const float4*)s;
    uint2 o; o.x = pkbf2(v.x, v.y); o.y = pkbf2(v.z, v.w);
    *(uint2*)d = o;
}

// ---------------- rank-1 layer-0 QKV precompute ----------------
__global__ void prep0_kernel(const float* __restrict__ Wqkv, const float* __restrict__ bqkv,
                             const float* __restrict__ W_emb, const float* __restrict__ b_emb)
{
    int wid = threadIdx.x >> 5, lane = threadIdx.x & 31;
    for (int j = wid; j < 768; j += 8){
        const float* row = Wqkv + (size_t)j*256;
        float su = 0.f, sc = 0.f;
        #pragma unroll
        for (int i=0;i<8;i++){
            float w = row[lane + i*32];
            su = fmaf(w, W_emb[lane + i*32], su);
            sc = fmaf(w, b_emb[lane + i*32], sc);
        }
        #pragma unroll
        for (int o=16;o>0;o>>=1){
            su += __shfl_xor_sync(0xffffffffu, su, o);
            sc += __shfl_xor_sync(0xffffffffu, sc, o);
        }
        if (lane == 0){ d_u[j] = su; d_c[j] = sc + bqkv[j]; }
    }
}

// ---------------- embed + layer-0 QKV (rank-1) ----------------
__global__ void embed0_kernel(const float* __restrict__ inputs,
                              const float* __restrict__ W_emb,
                              const float* __restrict__ b_emb)
{
    int tok = blockIdx.x;
    int d   = threadIdx.x;
    float y = __ldg(&inputs[(size_t)tok*4]);
    float v = fmaf(y, W_emb[d], b_emb[d]);
    d_Xb[(size_t)tok*DMODEL + d] = __float2bfloat16(v);   // bf16 residual stream
    #pragma unroll
    for (int t=0;t<3;t++){
        int j = d + t*256;
        float q = fmaf(y, d_u[j], d_c[j]);
        d_QKVb[(size_t)tok*768 + j] = __float2bfloat16(q);
    }
}

// ---------------- bf16 GEMM: 128x128 tile, BK=64, 3-stage, 1 sync/iter ----------------
#define G_STG (128*72)
#define GEMM_SMEM 110592
__global__ __launch_bounds__(256) void gemm_kernel(
    const __nv_bfloat16* __restrict__ A,
    const __nv_bfloat16* __restrict__ B,
    const float* __restrict__ bias,
    __nv_bfloat16* __restrict__ outB,
    int N, int K, int relu, int mStride, int mOff, int n0Add)
{
    extern __shared__ __align__(16) unsigned char dynsm[];
    __nv_bfloat16* As = (__nv_bfloat16*)dynsm;       // [3][128*72]
    __nv_bfloat16* Bs = As + 3*G_STG;                // [3][128*72]

    const int tid = threadIdx.x;
    const int wid = tid >> 5, lane = tid & 31;
    const int wm  = wid >> 1, wn = wid & 1;
    const int r8 = lane & 7, sel = lane >> 3;
    const int m0  = (blockIdx.y * mStride + mOff) * 128;
    const int n0  = blockIdx.x * 128 + n0Add;

    float c[2][8][4];
    #pragma unroll
    for (int x=0;x<2;x++)
        #pragma unroll
        for (int j=0;j<8;j++){ c[x][j][0]=0.f;c[x][j][1]=0.f;c[x][j][2]=0.f;c[x][j][3]=0.f; }

    const int kIter = K >> 6;

    auto issue = [&](int i, int bf){
        const __nv_bfloat16* Ag = A + (size_t)m0*K + i*64;
        const __nv_bfloat16* Bg = B + (size_t)n0*K + i*64;
        __nv_bfloat16* Ad = As + bf*G_STG;
        __nv_bfloat16* Bd = Bs + bf*G_STG;
        #pragma unroll
        for (int cc = tid; cc < 1024; cc += 256){
            int r = cc >> 3, off = (cc & 7)*8;
            CPA(smem_u32(&Ad[r*72+off]), Ag + (size_t)r*K + off);
            CPA(smem_u32(&Bd[r*72+off]), Bg + (size_t)r*K + off);
        }
    };

    issue(0, 0); CPC();
    if (kIter > 1){ issue(1, 1); CPC(); }

    int cur = 0;
    for (int i = 0; i < kIter; i++){
        if (i+1 < kIter) CPW1(); else CPW0();
        __syncthreads();
        if (i+2 < kIter){
            int st = cur+2; if (st>=3) st-=3;
            issue(i+2, st); CPC();
        }
        const __nv_bfloat16* Asb = As + cur*G_STG;
        const __nv_bfloat16* Bsb = Bs + cur*G_STG;

        #pragma unroll
        for (int half = 0; half < 2; half++){
            unsigned a[2][2][4];
            #pragma unroll
            for (int x=0;x<2;x++)
                #pragma unroll
                for (int t=0;t<2;t++){
                    int row = wm*32 + x*16 + (sel&1)*8 + r8;
                    unsigned addr = smem_u32(&Asb[row*72 + half*32 + t*16 + (sel>>1)*8]);
                    LDSM4(a[x][t][0], a[x][t][1], a[x][t][2], a[x][t][3], addr);
                }
            #pragma unroll
            for (int j=0;j<8;j++){
                unsigned b0,b1,b2,b3;
                unsigned addr = smem_u32(&Bsb[(wn*64 + j*8 + r8)*72 + half*32 + sel*8]);
                LDSM4(b0,b1,b2,b3, addr);
                #pragma unroll
                for (int x=0;x<2;x++){
                    MMA16816(c[x][j][0],c[x][j][1],c[x][j][2],c[x][j][3],
                             a[x][0][0],a[x][0][1],a[x][0][2],a[x][0][3], b0,b1);
                    MMA16816(c[x][j][0],c[x][j][1],c[x][j][2],c[x][j][3],
                             a[x][1][0],a[x][1][1],a[x][1][2],a[x][1][3], b2,b3);
                }
            }
        }
        cur = (cur+1 == 3) ? 0 : cur+1;
    }

    // register-direct epilogue (no smem, no sync)
    const int g = lane >> 2, tg = lane & 3;
    #pragma unroll
    for (int x=0;x<2;x++){
        int row0 = m0 + wm*32 + x*16 + g;
        #pragma unroll
        for (int j=0;j<8;j++){
            int col = n0 + wn*64 + j*8 + 2*tg;
            float b0 = bias[col], b1 = bias[col+1];
            float v00 = c[x][j][0] + b0, v01 = c[x][j][1] + b1;
            float v10 = c[x][j][2] + b0, v11 = c[x][j][3] + b1;
            if (relu){
                v00 = fmaxf(v00,0.f); v01 = fmaxf(v01,0.f);
                v10 = fmaxf(v10,0.f); v11 = fmaxf(v11,0.f);
            }
            *(unsigned*)&outB[(size_t)row0*N + col]     = pkbf2(v00, v01);
            *(unsigned*)&outB[(size_t)(row0+8)*N + col] = pkbf2(v10, v11);
        }
    }
}

// ---------------- GEMM + bias + resid(bf16) + LN fused: 64x256 tile, BK=32, 3-stage ----------------
#define GL_ASTG (64*40)
#define GL_BSTG (256*40)
#define GL_STG  (GL_ASTG + GL_BSTG)
__global__ __launch_bounds__(256) void gemm_ln_kernel(
    const __nv_bfloat16* __restrict__ A,
    const __nv_bfloat16* __restrict__ B,
    const float* __restrict__ bias,
    const float* __restrict__ g,
    const float* __restrict__ bta,
    int K, int sparse)
{
    extern __shared__ __align__(16) unsigned char dynsm[];
    __nv_bfloat16* St = (__nv_bfloat16*)dynsm;       // [3][A 64*40 | B 256*40]
    float*         Cs = (float*)dynsm;               // [32][264] epilogue alias

    const int tid = threadIdx.x;
    const int wid = tid >> 5, lane = tid & 31;
    const int wm  = wid >> 2, wn = wid & 3;
    const int r8 = lane & 7, sel = lane >> 3;
    const int t64 = sparse ? ((blockIdx.y >> 1)*32 + 30 + (blockIdx.y & 1)) : blockIdx.y;
    const int m0  = t64 * 64;

    float c[2][8][4];
    #pragma unroll
    for (int x=0;x<2;x++)
        #pragma unroll
        for (int j=0;j<8;j++){ c[x][j][0]=0.f;c[x][j][1]=0.f;c[x][j][2]=0.f;c[x][j][3]=0.f; }

    const int kIter = K >> 5;

    auto issue = [&](int i, int bf){
        const __nv_bfloat16* Ag = A + (size_t)m0*K + i*32;
        const __nv_bfloat16* Bg = B + i*32;
        __nv_bfloat16* Ad = St + bf*GL_STG;
        __nv_bfloat16* Bd = Ad + GL_ASTG;
        {
            int r = tid >> 2, off = (tid & 3)*8;
            CPA(smem_u32(&Ad[r*40+off]), Ag + (size_t)r*K + off);
        }
        #pragma unroll
        for (int cc = tid; cc < 1024; cc += 256){
            int r = cc >> 2, off = (cc & 3)*8;
            CPA(smem_u32(&Bd[r*40+off]), Bg + (size_t)r*K + off);
        }
    };

    issue(0, 0); CPC();
    if (kIter > 1){ issue(1, 1); CPC(); }

    int cur = 0;
    for (int i = 0; i < kIter; i++){
        if (i+1 < kIter) CPW1(); else CPW0();
        __syncthreads();
        if (i+2 < kIter){
            int st = cur+2; if (st>=3) st-=3;
            issue(i+2, st); CPC();
        }
        const __nv_bfloat16* Asb = St + cur*GL_STG;
        const __nv_bfloat16* Bsb = Asb + GL_ASTG;

        unsigned a[2][2][4];
        #pragma unroll
        for (int x=0;x<2;x++)
            #pragma unroll
            for (int t=0;t<2;t++){
                int row = wm*32 + x*16 + (sel&1)*8 + r8;
                unsigned addr = smem_u32(&Asb[row*40 + t*16 + (sel>>1)*8]);
                LDSM4(a[x][t][0], a[x][t][1], a[x][t][2], a[x][t][3], addr);
            }
        #pragma unroll
        for (int j=0;j<8;j++){
            unsigned b0,b1,b2,b3;
            unsigned addr = smem_u32(&Bsb[(wn*64 + j*8 + r8)*40 + sel*8]);
            LDSM4(b0,b1,b2,b3, addr);
            #pragma unroll
            for (int x=0;x<2;x++){
                MMA16816(c[x][j][0],c[x][j][1],c[x][j][2],c[x][j][3],
                         a[x][0][0],a[x][0][1],a[x][0][2],a[x][0][3], b0,b1);
                MMA16816(c[x][j][0],c[x][j][1],c[x][j][2],c[x][j][3],
                         a[x][1][0],a[x][1][1],a[x][1][2],a[x][1][3], b2,b3);
            }
        }
        cur = (cur+1 == 3) ? 0 : cur+1;
    }
    __syncthreads();   // all compute done before Cs aliases stage smem

    const int gq = lane >> 2, tg = lane & 3;
    #pragma unroll
    for (int chunk = 0; chunk < 2; chunk++){
        if (wm == chunk){
            #pragma unroll
            for (int x=0;x<2;x++){
                #pragma unroll
                for (int j=0;j<8;j++){
                    int colL = wn*64 + j*8 + 2*tg;
                    *(float2*)&Cs[(x*16 + gq)*264 + colL]     = make_float2(c[x][j][0], c[x][j][1]);
                    *(float2*)&Cs[(x*16 + gq + 8)*264 + colL] = make_float2(c[x][j][2], c[x][j][3]);
                }
            }
        }
        __syncthreads();
        #pragma unroll
        for (int ii=0; ii<4; ii++){
            int rloc = wid*4 + ii;
            int tok  = m0 + chunk*32 + rloc;
            float v[8]; float s = 0.f;
            #pragma unroll
            for (int i2=0;i2<4;i2++){
                int c0 = 2*lane + 64*i2;
                unsigned rb = *(const unsigned*)&d_Xb[(size_t)tok*DMODEL + c0];  // bf16x2 residual
                float r0 = __bfloat162float(*(__nv_bfloat16*)&rb);
                unsigned rbh = rb >> 16;
                float r1 = __bfloat162float(*(__nv_bfloat16*)&rbh);
                v[2*i2]   = Cs[rloc*264 + c0]   + bias[c0]   + r0;
                v[2*i2+1] = Cs[rloc*264 + c0+1] + bias[c0+1] + r1;
                s += v[2*i2] + v[2*i2+1];
            }
            #pragma unroll
            for (int o=16;o>0;o>>=1) s += __shfl_xor_sync(0xffffffffu, s, o);
            float mean = s * (1.f/256.f);
            float q = 0.f;
            #pragma unroll
            for (int i2=0;i2<8;i2++){ float dd = v[i2]-mean; q = fmaf(dd, dd, q); }
            #pragma unroll
            for (int o=16;o>0;o>>=1) q += __shfl_xor_sync(0xffffffffu, q, o);
            float rstd = rsqrtf(q*(1.f/256.f) + 1e-5f);
            #pragma unroll
            for (int i2=0;i2<4;i2++){
                int c0 = 2*lane + 64*i2;
                float o0 = (v[2*i2]  -mean)*rstd*g[c0]   + bta[c0];
                float o1 = (v[2*i2+1]-mean)*rstd*g[c0+1] + bta[c0+1];
                *(unsigned*)&d_Xb[(size_t)tok*DMODEL + c0] = pkbf2(o0, o1);
            }
        }
        __syncthreads();
    }
}

// ---------------- flash attention: 128 q rows, 3-stage K/V, 1 sync/iter (round-12 proven) ----------------
#define A_STG (128*40)
__global__ __launch_bounds__(256, 3) void attn_kernel(int qtBase, int useMax)
{
    extern __shared__ __align__(16) unsigned char dynsm_a[];
    __nv_bfloat16* Qs = (__nv_bfloat16*)dynsm_a;     // 128*40
    __nv_bfloat16* Ks = Qs + A_STG;                  // [3][128*40]
    __nv_bfloat16* Vs = Ks + 3*A_STG;                // [3][128*40]

    const int tid = threadIdx.x, lane = tid & 31, w = tid >> 5;
    const int qt = qtBase - blockIdx.x;              // heavy tiles first
    const int bh = blockIdx.y, b = bh >> 3, h = bh & 7;
    const int g = lane >> 2, tig = lane & 3;
    const int r8 = lane & 7, sel = lane >> 3;
    const int rwBase = qt*128 + w*16;

    auto issueKV = [&](int kt, int st){
        const __nv_bfloat16* Kg = d_QKVb + ((size_t)(b*SEQ + kt*128))*768 + 256 + h*32;
        #pragma unroll
        for (int cc = tid; cc < 512; cc += 256){
            int r = cc >> 2, off = (cc & 3)*8;
            CPA(smem_u32(&Ks[st*A_STG + r*40+off]), Kg + (size_t)r*768 + off);
            CPA(smem_u32(&Vs[st*A_STG + r*40+off]), Kg + 256 + (size_t)r*768 + off);
        }
    };

    {
        const __nv_bfloat16* Qg = d_QKVb + ((size_t)(b*SEQ + qt*128))*768 + h*32;
        #pragma unroll
        for (int cc = tid; cc < 512; cc += 256){
            int r = cc >> 2, off = (cc & 3)*8;
            CPA(smem_u32(&Qs[r*40+off]), Qg + (size_t)r*768 + off);
        }
        issueKV(0, 0); CPC();
        if (qt >= 1){ issueKV(1, 1); CPC(); }
    }

    unsigned aq[2][4];
    float o[4][4];
    #pragma unroll
    for (int j=0;j<4;j++){ o[j][0]=0.f;o[j][1]=0.f;o[j][2]=0.f;o[j][3]=0.f; }
    float l0 = 0.f, l1 = 0.f;
    float m0v = -1e30f, m1v = -1e30f;
    const int gr0 = rwBase + g;

    int cur = 0;
    for (int kt = 0; kt <= qt; kt++){
        if (kt < qt) CPW1(); else CPW0();
        __syncthreads();
        if (kt == 0){
            int row = w*16 + (sel & 1)*8 + r8;
            #pragma unroll
            for (int t=0;t<2;t++){
                unsigned addr = smem_u32(&Qs[row*40 + t*16 + (sel>>1)*8]);
                LDSM4(aq[t][0], aq[t][1], aq[t][2], aq[t][3], addr);
            }
        }
        if (kt+2 <= qt){
            int st = cur+2; if (st>=3) st-=3;
            issueKV(kt+2, st); CPC();
        }

        const __nv_bfloat16* Kb = Ks + cur*A_STG;
        const __nv_bfloat16* Vb = Vs + cur*A_STG;

        #pragma unroll
        for (int h2 = 0; h2 < 2; h2++){
            const int cb = kt*128 + h2*64;
            if (cb > rwBase + 15) break;

            float s[8][4];
            #pragma unroll
            for (int j=0;j<8;j++){
                s[j][0]=0.f;s[j][1]=0.f;s[j][2]=0.f;s[j][3]=0.f;
                unsigned k0,k1,k2,k3;
                unsigned addr = smem_u32(&Kb[(h2*64 + j*8 + r8)*40 + sel*8]);
                LDSM4(k0,k1,k2,k3, addr);
                MMA16816(s[j][0],s[j][1],s[j][2],s[j][3],
                         aq[0][0],aq[0][1],aq[0][2],aq[0][3], k0,k1);
                MMA16816(s[j][0],s[j][1],s[j][2],s[j][3],
                         aq[1][0],aq[1][1],aq[1][2],aq[1][3], k2,k3);
            }

            const bool diag = (cb + 63 > rwBase);
            if (diag){
                #pragma unroll
                for (int j=0;j<8;j++){
                    int c0 = cb + j*8 + 2*tig;
                    if (c0   > gr0)   s[j][0] = -1e30f;
                    if (c0+1 > gr0)   s[j][1] = -1e30f;
                    if (c0   > gr0+8) s[j][2] = -1e30f;
                    if (c0+1 > gr0+8) s[j][3] = -1e30f;
                }
            }

            float base0 = EXP_B0, base1 = EXP_B0;
            if (useMax){
                float mt0 = -1e30f, mt1 = -1e30f;
                #pragma unroll
                for (int j=0;j<8;j++){
                    mt0 = fmaxf(mt0, fmaxf(s[j][0], s[j][1]));
                    mt1 = fmaxf(mt1, fmaxf(s[j][2], s[j][3]));
                }
                mt0 = fmaxf(mt0, __shfl_xor_sync(0xffffffffu, mt0, 1));
                mt0 = fmaxf(mt0, __shfl_xor_sync(0xffffffffu, mt0, 2));
                mt1 = fmaxf(mt1, __shfl_xor_sync(0xffffffffu, mt1, 1));
                mt1 = fmaxf(mt1, __shfl_xor_sync(0xffffffffu, mt1, 2));
                float nm0 = fmaxf(m0v, mt0), nm1 = fmaxf(m1v, mt1);
                base0 = EXP_B0 - EXP_SA*nm0;
                base1 = EXP_B0 - EXP_SA*nm1;
                float corr0 = cexpb(m0v, base0), corr1 = cexpb(m1v, base1);
                m0v = nm0; m1v = nm1;
                l0 *= corr0; l1 *= corr1;
                #pragma unroll
                for (int j=0;j<4;j++){
                    o[j][0] *= corr0; o[j][1] *= corr0;
                    o[j][2] *= corr1; o[j][3] *= corr1;
                }
            }

            const bool clampP = useMax || diag;
            unsigned pp[4][4];
            #pragma unroll
            for (int t=0;t<4;t++){
                float t00 = fmaf(s[2*t][0],   EXP_SA, base0), t01 = fmaf(s[2*t][1],   EXP_SA, base0);
                float t02 = fmaf(s[2*t][2],   EXP_SA, base1), t03 = fmaf(s[2*t][3],   EXP_SA, base1);
                float t10 = fmaf(s[2*t+1][0], EXP_SA, base0), t11 = fmaf(s[2*t+1][1], EXP_SA, base0);
                float t12 = fmaf(s[2*t+1][2], EXP_SA, base1), t13 = fmaf(s[2*t+1][3], EXP_SA, base1);
                if (clampP){
                    t00 = fmaxf(t00,0.f); t01 = fmaxf(t01,0.f);
                    t02 = fmaxf(t02,0.f); t03 = fmaxf(t03,0.f);
                    t10 = fmaxf(t10,0.f); t11 = fmaxf(t11,0.f);
                    t12 = fmaxf(t12,0.f); t13 = fmaxf(t13,0.f);
                }
                int i00 = (int)t00, i01 = (int)t01, i02 = (int)t02, i03 = (int)t03;
                int i10 = (int)t10, i11 = (int)t11, i12 = (int)t12, i13 = (int)t13;
                l0 += __int_as_float(i00) + __int_as_float(i01)
                    + __int_as_float(i10) + __int_as_float(i11);
                l1 += __int_as_float(i02) + __int_as_float(i03)
                    + __int_as_float(i12) + __int_as_float(i13);
                pp[t][0] = prmt_hi((unsigned)i00, (unsigned)i01);
                pp[t][1] = prmt_hi((unsigned)i02, (unsigned)i03);
                pp[t][2] = prmt_hi((unsigned)i10, (unsigned)i11);
                pp[t][3] = prmt_hi((unsigned)i12, (unsigned)i13);
            }

            #pragma unroll
            for (int t=0;t<4;t++){
                unsigned v0,v1,v2,v3, x0,x1,x2,x3;
                int vrow = h2*64 + 16*t + (sel & 1)*8 + r8;
                unsigned addrA = smem_u32(&Vb[vrow*40 + (sel>>1)*8]);
                unsigned addrB = smem_u32(&Vb[vrow*40 + 16 + (sel>>1)*8]);
                LDSM4T(v0,v1,v2,v3, addrA);
                LDSM4T(x0,x1,x2,x3, addrB);
                MMA16816(o[0][0],o[0][1],o[0][2],o[0][3], pp[t][0],pp[t][1],pp[t][2],pp[t][3], v0,v1);
                MMA16816(o[1][0],o[1][1],o[1][2],o[1][3], pp[t][0],pp[t][1],pp[t][2],pp[t][3], v2,v3);
                MMA16816(o[2][0],o[2][1],o[2][2],o[2][3], pp[t][0],pp[t][1],pp[t][2],pp[t][3], x0,x1);
                MMA16816(o[3][0],o[3][1],o[3][2],o[3][3], pp[t][0],pp[t][1],pp[t][2],pp[t][3], x2,x3);
            }
        }
        cur = (cur+1 == 3) ? 0 : cur+1;
    }

    l0 += __shfl_xor_sync(0xffffffffu, l0, 1);
    l0 += __shfl_xor_sync(0xffffffffu, l0, 2);
    l1 += __shfl_xor_sync(0xffffffffu, l1, 1);
    l1 += __shfl_xor_sync(0xffffffffu, l1, 2);
    float rl0 = __fdividef(1.f, l0), rl1 = __fdividef(1.f, l1);
    __nv_bfloat16* Og0 = d_ATTb + ((size_t)(b*SEQ + rwBase + g))*256 + h*32;
    __nv_bfloat16* Og1 = Og0 + (size_t)8*256;
    #pragma unroll
    for (int j=0;j<4;j++){
        int dcol = j*8 + 2*tig;
        *(unsigned*)&Og0[dcol] = pkbf2(o[j][0]*rl0, o[j][1]*rl0);
        *(unsigned*)&Og1[dcol] = pkbf2(o[j][2]*rl1, o[j][3]*rl1);
    }
}

// ---------------- dec + hist + IDM + fusion ----------------
__global__ void final_kernel(const float* __restrict__ inputs,
    const float* __restrict__ his,
    const float* __restrict__ W_dec, const float* __restrict__ b_dec,
    const float* __restrict__ W_fus, const float* __restrict__ b_fus,
    float* __restrict__ out)
{
    __shared__ float dec[8], yidm[8][LOUT], lastpos[8], dvb[8];
    int tid = threadIdx.x, wid = tid>>5, lane = tid&31;
    {
        const __nv_bfloat16* row = d_Xb + ((size_t)(wid*SEQ + SEQ-1))*DMODEL;
        float s = 0.f;
        #pragma unroll
        for (int i=0;i<8;i++){
            int d_ = lane + i*32;
            s = fmaf(__bfloat162float(row[d_]), W_dec[d_], s);
        }
        #pragma unroll
        for (int o=16;o>0;o>>=1) s += __shfl_xor_sync(0xffffffffu, s, o);
        if (lane==0) dec[wid] = s + b_dec[0];
    }
    if (tid < 8){
        int b = tid;
        float lp = inputs[((size_t)(b*SEQ + SEQ-1))*4];
        lastpos[b] = lp;
        dvb[b] = (lp - inputs[((size_t)(b*SEQ + SEQ-1-LOUT))*4]) / 50.f;
    }
    __syncthreads();

    if (tid < 8){
        int b = tid;
        const float* il = inputs + ((size_t)(b*SEQ + SEQ-1))*4;
        float y = il[0], v = il[1], sg = il[2], dv = il[3];
        const float sqab2 = 2.449489742783178f;
        float sx = 2.0f + fmaxf(0.f, v*1.5f + v*dv/sqab2);
        float t = v/30.0f; float p = t*t; p *= p;
        float rr = sx/sg;
        float af = (1.f - p - rr*rr);
        float v0 = fmaxf(v + af*0.1f, 0.f);
        float v0last = __shfl_sync(0xffu, v0, 7);   // reference's v0[-1] broadcast
        float yp = y + v0last*0.1f;
        float vp = v0;
        yidm[b][0] = yp;
        for (int j=0;j<LOUT-1;j++){
            float hp = his[((size_t)(b*LOUT + j))*2];
            float hv = his[((size_t)(b*LOUT + j))*2 + 1];
            float dvj = hv - vp;
            float sj  = hp - yp;
            float sxj = 2.0f + fmaxf(0.f, vp*1.5f + vp*dvj/sqab2);
            float tt = vp/30.0f; float q4 = tt*tt; q4 *= q4;
            float r2 = sxj/sj;
            float acc = (1.f - q4 - r2*r2);
            float v2 = vp + acc*0.1f;
            v2 = (v2 <= 0.f) ? 0.f : v2;
            yp = yp + v2*0.1f;
            yidm[b][j+1] = yp;
            vp = v2;
        }
    }
    __syncthreads();

    float w0 = W_fus[0], w1 = W_fus[1], w2 = W_fus[2], bb = b_fus[0];
    for (int t = tid; t < BATCH*LOUT; t += 256){
        int b = t / LOUT, l = t % LOUT;
        out[t] = w0*dec[b] + w1*(lastpos[b] + dvb[b]*(float)(l+1)) + w2*yidm[b][l] + bb;
    }
}

// ---------------- launcher ----------------
#define GLN_SMEM    76800
#define ATT_SMEM    71680

extern "C" void kernel_launch(void* const* d_in, const int* in_sizes, int n_in,
                              void* d_out, int out_size)
{
    (void)in_sizes; (void)n_in; (void)out_size;
    const float* inputs = (const float*)d_in[0];
    const float* his    = (const float*)d_in[1];
    const float* W_emb  = (const float*)d_in[2];
    const float* b_emb  = (const float*)d_in[3];
    const float* Wqkv   = (const float*)d_in[4];
    const float* bqkv   = (const float*)d_in[5];
    const float* Wo     = (const float*)d_in[6];
    const float* bo     = (const float*)d_in[7];
    const float* W1     = (const float*)d_in[8];
    const float* b1     = (const float*)d_in[9];
    const float* W2     = (const float*)d_in[10];
    const float* b2     = (const float*)d_in[11];
    const float* ln1g   = (const float*)d_in[12];
    const float* ln1b   = (const float*)d_in[13];
    const float* ln2g   = (const float*)d_in[14];
    const float* ln2b   = (const float*)d_in[15];
    const float* W_dec  = (const float*)d_in[16];
    const float* b_dec  = (const float*)d_in[17];
    const float* W_fus  = (const float*)d_in[18];
    const float* b_fus  = (const float*)d_in[19];
    float* out = (float*)d_out;

    cudaFuncSetAttribute(gemm_kernel,    cudaFuncAttributeMaxDynamicSharedMemorySize, GEMM_SMEM);
    cudaFuncSetAttribute(gemm_ln_kernel, cudaFuncAttributeMaxDynamicSharedMemorySize, GLN_SMEM);
    cudaFuncSetAttribute(attn_kernel,    cudaFuncAttributeMaxDynamicSharedMemorySize, ATT_SMEM);

    void *pXb_, *pHb_, *pWq_, *pWo_, *pW1_, *pW2_, *pATT_, *pQKV_;
    cudaGetSymbolAddress(&pXb_,  d_Xb);
    cudaGetSymbolAddress(&pHb_,  d_Hb);
    cudaGetSymbolAddress(&pWq_,  d_WqkvB);
    cudaGetSymbolAddress(&pWo_,  d_WoB);
    cudaGetSymbolAddress(&pW1_,  d_W1B);
    cudaGetSymbolAddress(&pW2_,  d_W2B);
    cudaGetSymbolAddress(&pATT_, d_ATTb);
    cudaGetSymbolAddress(&pQKV_, d_QKVb);

    __nv_bfloat16* Xb   = (__nv_bfloat16*)pXb_;
    __nv_bfloat16* Hb   = (__nv_bfloat16*)pHb_;
    __nv_bfloat16* WqB  = (__nv_bfloat16*)pWq_;
    __nv_bfloat16* WoB  = (__nv_bfloat16*)pWo_;
    __nv_bfloat16* W1B  = (__nv_bfloat16*)pW1_;
    __nv_bfloat16* W2B  = (__nv_bfloat16*)pW2_;
    __nv_bfloat16* ATTb = (__nv_bfloat16*)pATT_;
    __nv_bfloat16* QKVb = (__nv_bfloat16*)pQKV_;

    conv4_kernel<<<(N0+N1+N2+N3)/4/256, 256>>>(Wqkv, Wo, W1, W2);
    prep0_kernel<<<1, 256>>>(Wqkv, bqkv, W_emb, b_emb);
    embed0_kernel<<<NTOK, 256>>>(inputs, W_emb, b_emb);

    for (int l = 0; l < NLAY; l++){
        int sp = (l == NLAY-1);
        int useMax = (l == 0);

        if (l > 0){
            if (!sp){
                gemm_kernel<<<dim3(6,128), 256, GEMM_SMEM>>>(Xb, WqB + (size_t)l*768*256,
                    bqkv + l*768, QKVb, 768, 256, 0, 1, 0, 0);
            } else {
                gemm_kernel<<<dim3(4,128), 256, GEMM_SMEM>>>(Xb, WqB + (size_t)l*768*256,
                    bqkv + l*768, QKVb, 768, 256, 0, 1, 0, 256);
                gemm_kernel<<<dim3(2,8), 256, GEMM_SMEM>>>(Xb, WqB + (size_t)l*768*256,
                    bqkv + l*768, QKVb, 768, 256, 0, 16, 15, 0);
            }
        }

        if (!sp) attn_kernel<<<dim3(16,64), 256, ATT_SMEM>>>(15, useMax);
        else     attn_kernel<<<dim3(1,64),  256, ATT_SMEM>>>(15, useMax);

        gemm_ln_kernel<<<dim3(1, sp?16:256), 256, GLN_SMEM>>>(ATTb, WoB + (size_t)l*256*256,
            bo + l*256, ln1g + l*256, ln1b + l*256, 256, sp);

        gemm_kernel<<<dim3(8, sp?8:128), 256, GEMM_SMEM>>>(Xb, W1B + (size_t)l*1024*256,
            b1 + l*1024, Hb, 1024, 256, 1, sp?16:1, sp?15:0, 0);

        gemm_ln_kernel<<<dim3(1, sp?16:256), 256, GLN_SMEM>>>(Hb, W2B + (size_t)l*256*1024,
            b2 + l*256, ln2g + l*256, ln2b + l*256, 1024, sp);
    }

    final_kernel<<<1, 256>>>(inputs, his, W_dec, b_dec, W_fus, b_fus, out);
}

// round 15
// speedup vs baseline: 1.0504x; 1.0120x over previous
#include <cuda_runtime.h>
#include <cuda_bf16.h>

// ---------------- problem constants ----------------
#define BATCH   8
#define SEQ     2048
#define DMODEL  256
#define NHEAD   8
#define DHEAD   32
#define NHID    1024
#define NLAY    4
#define NTOK    (BATCH*SEQ)        // 16384
#define LOUT    50
#define ATT_SCALE 0.17677669529663687f   // 1/sqrt(32)

// ---------------- scratch ----------------
__device__ __align__(256) __nv_bfloat16  d_Xb  [NTOK*DMODEL];   // activations+residual (bf16 only)
__device__ __align__(256) __nv_bfloat16  d_QKVb[NTOK*3*DMODEL];
__device__ __align__(256) __nv_bfloat16  d_ATTb[NTOK*DMODEL];
__device__ __align__(256) __nv_bfloat16  d_Hb  [NTOK*NHID];
__device__ __align__(256) __nv_bfloat16  d_WqkvB[NLAY*3*DMODEL*DMODEL];
__device__ __align__(256) __nv_bfloat16  d_WoB  [NLAY*DMODEL*DMODEL];
__device__ __align__(256) __nv_bfloat16  d_W1B  [NLAY*NHID*DMODEL];
__device__ __align__(256) __nv_bfloat16  d_W2B  [NLAY*DMODEL*NHID];
__device__ __align__(256) float          d_u[768];
__device__ __align__(256) float          d_c[768];

// ---------------- PTX helpers ----------------
__device__ __forceinline__ unsigned smem_u32(const void* p){
    return (unsigned)__cvta_generic_to_shared(p);
}
#define CPA(dst, src) asm volatile("cp.async.cg.shared.global [%0], [%1], 16;" :: "r"(dst), "l"(src))
#define CPC() asm volatile("cp.async.commit_group;")
#define CPW0() asm volatile("cp.async.wait_group 0;")
#define CPW1() asm volatile("cp.async.wait_group 1;")
#define LDSM4(r0,r1,r2,r3,a) asm volatile("ldmatrix.sync.aligned.m8n8.x4.shared.b16 {%0,%1,%2,%3}, [%4];" \
    : "=r"(r0),"=r"(r1),"=r"(r2),"=r"(r3) : "r"(a))
#define LDSM4T(r0,r1,r2,r3,a) asm volatile("ldmatrix.sync.aligned.m8n8.x4.trans.shared.b16 {%0,%1,%2,%3}, [%4];" \
    : "=r"(r0),"=r"(r1),"=r"(r2),"=r"(r3) : "r"(a))
#define MMA16816(d0,d1,d2,d3, a0,a1,a2,a3, b0,b1) \
    asm volatile("mma.sync.aligned.m16n8k16.row.col.f32.bf16.bf16.f32 " \
        "{%0,%1,%2,%3}, {%4,%5,%6,%7}, {%8,%9}, {%0,%1,%2,%3};" \
        : "+f"(d0),"+f"(d1),"+f"(d2),"+f"(d3) \
        : "r"(a0),"r"(a1),"r"(a2),"r"(a3), "r"(b0),"r"(b1))

__device__ __forceinline__ unsigned pkbf2(float lo, float hi){
    unsigned d;
    asm("cvt.rn.bf16x2.f32 %0, %1, %2;" : "=r"(d) : "f"(hi), "f"(lo));
    return d;
}
__device__ __forceinline__ unsigned prmt_hi(unsigned a, unsigned b){
    unsigned d;
    asm("prmt.b32 %0, %1, %2, 0x7632;" : "=r"(d) : "r"(a), "r"(b));
    return d;
}
#define EXP_B0 1064986316.0f
#define EXP_SA (12102203.161f * ATT_SCALE)
__device__ __forceinline__ float cexpb(float s, float base){
    float t = fmaf(s, EXP_SA, base);
    t = fmaxf(t, 0.f);
    return __int_as_float((int)t);
}

// ---------------- merged weight conversion ----------------
#define N0 (NLAY*768*256)
#define N1 (NLAY*256*256)
#define N2 (NLAY*NHID*256)
#define N3 (NLAY*256*NHID)
__global__ void conv4_kernel(const float* __restrict__ s0, const float* __restrict__ s1,
                             const float* __restrict__ s2, const float* __restrict__ s3)
{
    int i = (blockIdx.x*blockDim.x + threadIdx.x)*4;
    const float* s; __nv_bfloat16* d;
    if      (i < N0)         { s = s0 + i;              d = d_WqkvB + i; }
    else if (i < N0+N1)      { s = s1 + (i-N0);         d = d_WoB  + (i-N0); }
    else if (i < N0+N1+N2)   { s = s2 + (i-N0-N1);      d = d_W1B  + (i-N0-N1); }
    else                     { s = s3 + (i-N0-N1-N2);   d = d_W2B  + (i-N0-N1-N2); }
    float4 v = *(const float4*)s;
    uint2 o; o.x = pkbf2(v.x, v.y); o.y = pkbf2(v.z, v.w);
    *(uint2*)d = o;
}

// ---------------- rank-1 layer-0 QKV precompute ----------------
__global__ void prep0_kernel(const float* __restrict__ Wqkv, const float* __restrict__ bqkv,
                             const float* __restrict__ W_emb, const float* __restrict__ b_emb)
{
    int wid = threadIdx.x >> 5, lane = threadIdx.x & 31;
    for (int j = wid; j < 768; j += 8){
        const float* row = Wqkv + (size_t)j*256;
        float su = 0.f, sc = 0.f;
        #pragma unroll
        for (int i=0;i<8;i++){
            float w = row[lane + i*32];
            su = fmaf(w, W_emb[lane + i*32], su);
            sc = fmaf(w, b_emb[lane + i*32], sc);
        }
        #pragma unroll
        for (int o=16;o>0;o>>=1){
            su += __shfl_xor_sync(0xffffffffu, su, o);
            sc += __shfl_xor_sync(0xffffffffu, sc, o);
        }
        if (lane == 0){ d_u[j] = su; d_c[j] = sc + bqkv[j]; }
    }
}

// ---------------- embed + layer-0 QKV (rank-1), vectorized x2 ----------------
__global__ void embed0_kernel(const float* __restrict__ inputs,
                              const float* __restrict__ W_emb,
                              const float* __restrict__ b_emb)
{
    int tok = blockIdx.x;
    int d2  = threadIdx.x*2;
    float y = __ldg(&inputs[(size_t)tok*4]);
    float v0 = fmaf(y, W_emb[d2],   b_emb[d2]);
    float v1 = fmaf(y, W_emb[d2+1], b_emb[d2+1]);
    *(unsigned*)&d_Xb[(size_t)tok*DMODEL + d2] = pkbf2(v0, v1);
    #pragma unroll
    for (int t=0;t<3;t++){
        int j = d2 + t*256;
        float q0 = fmaf(y, d_u[j],   d_c[j]);
        float q1 = fmaf(y, d_u[j+1], d_c[j+1]);
        *(unsigned*)&d_QKVb[(size_t)tok*768 + j] = pkbf2(q0, q1);
    }
}

// ---------------- bf16 GEMM: 128x128 tile, BK=64, 3-stage, 1 sync/iter ----------------
#define G_STG (128*72)
#define GEMM_SMEM 110592
__global__ __launch_bounds__(256) void gemm_kernel(
    const __nv_bfloat16* __restrict__ A,
    const __nv_bfloat16* __restrict__ B,
    const float* __restrict__ bias,
    __nv_bfloat16* __restrict__ outB,
    int N, int K, int relu, int mStride, int mOff, int n0Add)
{
    extern __shared__ __align__(16) unsigned char dynsm[];
    __nv_bfloat16* As = (__nv_bfloat16*)dynsm;       // [3][128*72]
    __nv_bfloat16* Bs = As + 3*G_STG;                // [3][128*72]

    const int tid = threadIdx.x;
    const int wid = tid >> 5, lane = tid & 31;
    const int wm  = wid >> 1, wn = wid & 1;
    const int r8 = lane & 7, sel = lane >> 3;
    const int m0  = (blockIdx.y * mStride + mOff) * 128;
    const int n0  = blockIdx.x * 128 + n0Add;

    float c[2][8][4];
    #pragma unroll
    for (int x=0;x<2;x++)
        #pragma unroll
        for (int j=0;j<8;j++){ c[x][j][0]=0.f;c[x][j][1]=0.f;c[x][j][2]=0.f;c[x][j][3]=0.f; }

    const int kIter = K >> 6;

    auto issue = [&](int i, int bf){
        const __nv_bfloat16* Ag = A + (size_t)m0*K + i*64;
        const __nv_bfloat16* Bg = B + (size_t)n0*K + i*64;
        __nv_bfloat16* Ad = As + bf*G_STG;
        __nv_bfloat16* Bd = Bs + bf*G_STG;
        #pragma unroll
        for (int cc = tid; cc < 1024; cc += 256){
            int r = cc >> 3, off = (cc & 7)*8;
            CPA(smem_u32(&Ad[r*72+off]), Ag + (size_t)r*K + off);
            CPA(smem_u32(&Bd[r*72+off]), Bg + (size_t)r*K + off);
        }
    };

    issue(0, 0); CPC();
    if (kIter > 1){ issue(1, 1); CPC(); }

    int cur = 0;
    for (int i = 0; i < kIter; i++){
        if (i+1 < kIter) CPW1(); else CPW0();
        __syncthreads();
        if (i+2 < kIter){
            int st = cur+2; if (st>=3) st-=3;
            issue(i+2, st); CPC();
        }
        const __nv_bfloat16* Asb = As + cur*G_STG;
        const __nv_bfloat16* Bsb = Bs + cur*G_STG;

        #pragma unroll
        for (int half = 0; half < 2; half++){
            unsigned a[2][2][4];
            #pragma unroll
            for (int x=0;x<2;x++)
                #pragma unroll
                for (int t=0;t<2;t++){
                    int row = wm*32 + x*16 + (sel&1)*8 + r8;
                    unsigned addr = smem_u32(&Asb[row*72 + half*32 + t*16 + (sel>>1)*8]);
                    LDSM4(a[x][t][0], a[x][t][1], a[x][t][2], a[x][t][3], addr);
                }
            #pragma unroll
            for (int j=0;j<8;j++){
                unsigned b0,b1,b2,b3;
                unsigned addr = smem_u32(&Bsb[(wn*64 + j*8 + r8)*72 + half*32 + sel*8]);
                LDSM4(b0,b1,b2,b3, addr);
                #pragma unroll
                for (int x=0;x<2;x++){
                    MMA16816(c[x][j][0],c[x][j][1],c[x][j][2],c[x][j][3],
                             a[x][0][0],a[x][0][1],a[x][0][2],a[x][0][3], b0,b1);
                    MMA16816(c[x][j][0],c[x][j][1],c[x][j][2],c[x][j][3],
                             a[x][1][0],a[x][1][1],a[x][1][2],a[x][1][3], b2,b3);
                }
            }
        }
        cur = (cur+1 == 3) ? 0 : cur+1;
    }

    // register-direct epilogue (no smem, no sync)
    const int g = lane >> 2, tg = lane & 3;
    #pragma unroll
    for (int x=0;x<2;x++){
        int row0 = m0 + wm*32 + x*16 + g;
        #pragma unroll
        for (int j=0;j<8;j++){
            int col = n0 + wn*64 + j*8 + 2*tg;
            float b0 = bias[col], b1 = bias[col+1];
            float v00 = c[x][j][0] + b0, v01 = c[x][j][1] + b1;
            float v10 = c[x][j][2] + b0, v11 = c[x][j][3] + b1;
            if (relu){
                v00 = fmaxf(v00,0.f); v01 = fmaxf(v01,0.f);
                v10 = fmaxf(v10,0.f); v11 = fmaxf(v11,0.f);
            }
            *(unsigned*)&outB[(size_t)row0*N + col]     = pkbf2(v00, v01);
            *(unsigned*)&outB[(size_t)(row0+8)*N + col] = pkbf2(v10, v11);
        }
    }
}

// ---------------- GEMM + bias + resid(bf16) + LN fused: 64x256 tile, BK=32, 3-stage ----------------
#define GL_ASTG (64*40)
#define GL_BSTG (256*40)
#define GL_STG  (GL_ASTG + GL_BSTG)
__global__ __launch_bounds__(256) void gemm_ln_kernel(
    const __nv_bfloat16* __restrict__ A,
    const __nv_bfloat16* __restrict__ B,
    const float* __restrict__ bias,
    const float* __restrict__ g,
    const float* __restrict__ bta,
    int K, int sparse)
{
    extern __shared__ __align__(16) unsigned char dynsm[];
    __nv_bfloat16* St = (__nv_bfloat16*)dynsm;       // [3][A 64*40 | B 256*40]
    float*         Cs = (float*)dynsm;               // [32][264] epilogue alias

    const int tid = threadIdx.x;
    const int wid = tid >> 5, lane = tid & 31;
    const int wm  = wid >> 2, wn = wid & 3;
    const int r8 = lane & 7, sel = lane >> 3;
    const int t64 = sparse ? (blockIdx.y*32 + 31) : blockIdx.y;   // last 64-row tile per batch
    const int m0  = t64 * 64;

    float c[2][8][4];
    #pragma unroll
    for (int x=0;x<2;x++)
        #pragma unroll
        for (int j=0;j<8;j++){ c[x][j][0]=0.f;c[x][j][1]=0.f;c[x][j][2]=0.f;c[x][j][3]=0.f; }

    const int kIter = K >> 5;

    auto issue = [&](int i, int bf){
        const __nv_bfloat16* Ag = A + (size_t)m0*K + i*32;
        const __nv_bfloat16* Bg = B + i*32;
        __nv_bfloat16* Ad = St + bf*GL_STG;
        __nv_bfloat16* Bd = Ad + GL_ASTG;
        {
            int r = tid >> 2, off = (tid & 3)*8;
            CPA(smem_u32(&Ad[r*40+off]), Ag + (size_t)r*K + off);
        }
        #pragma unroll
        for (int cc = tid; cc < 1024; cc += 256){
            int r = cc >> 2, off = (cc & 3)*8;
            CPA(smem_u32(&Bd[r*40+off]), Bg + (size_t)r*K + off);
        }
    };

    issue(0, 0); CPC();
    if (kIter > 1){ issue(1, 1); CPC(); }

    int cur = 0;
    for (int i = 0; i < kIter; i++){
        if (i+1 < kIter) CPW1(); else CPW0();
        __syncthreads();
        if (i+2 < kIter){
            int st = cur+2; if (st>=3) st-=3;
            issue(i+2, st); CPC();
        }
        const __nv_bfloat16* Asb = St + cur*GL_STG;
        const __nv_bfloat16* Bsb = Asb + GL_ASTG;

        unsigned a[2][2][4];
        #pragma unroll
        for (int x=0;x<2;x++)
            #pragma unroll
            for (int t=0;t<2;t++){
                int row = wm*32 + x*16 + (sel&1)*8 + r8;
                unsigned addr = smem_u32(&Asb[row*40 + t*16 + (sel>>1)*8]);
                LDSM4(a[x][t][0], a[x][t][1], a[x][t][2], a[x][t][3], addr);
            }
        #pragma unroll
        for (int j=0;j<8;j++){
            unsigned b0,b1,b2,b3;
            unsigned addr = smem_u32(&Bsb[(wn*64 + j*8 + r8)*40 + sel*8]);
            LDSM4(b0,b1,b2,b3, addr);
            #pragma unroll
            for (int x=0;x<2;x++){
                MMA16816(c[x][j][0],c[x][j][1],c[x][j][2],c[x][j][3],
                         a[x][0][0],a[x][0][1],a[x][0][2],a[x][0][3], b0,b1);
                MMA16816(c[x][j][0],c[x][j][1],c[x][j][2],c[x][j][3],
                         a[x][1][0],a[x][1][1],a[x][1][2],a[x][1][3], b2,b3);
            }
        }
        cur = (cur+1 == 3) ? 0 : cur+1;
    }
    __syncthreads();   // all compute done before Cs aliases stage smem

    const int gq = lane >> 2, tg = lane & 3;
    #pragma unroll
    for (int chunk = 0; chunk < 2; chunk++){
        if (wm == chunk){
            #pragma unroll
            for (int x=0;x<2;x++){
                #pragma unroll
                for (int j=0;j<8;j++){
                    int colL = wn*64 + j*8 + 2*tg;
                    *(float2*)&Cs[(x*16 + gq)*264 + colL]     = make_float2(c[x][j][0], c[x][j][1]);
                    *(float2*)&Cs[(x*16 + gq + 8)*264 + colL] = make_float2(c[x][j][2], c[x][j][3]);
                }
            }
        }
        __syncthreads();
        #pragma unroll
        for (int ii=0; ii<4; ii++){
            int rloc = wid*4 + ii;
            int tok  = m0 + chunk*32 + rloc;
            float v[8]; float s = 0.f;
            #pragma unroll
            for (int i2=0;i2<4;i2++){
                int c0 = 2*lane + 64*i2;
                unsigned rb = *(const unsigned*)&d_Xb[(size_t)tok*DMODEL + c0];  // bf16x2 residual
                float r0 = __bfloat162float(*(__nv_bfloat16*)&rb);
                unsigned rbh = rb >> 16;
                float r1 = __bfloat162float(*(__nv_bfloat16*)&rbh);
                v[2*i2]   = Cs[rloc*264 + c0]   + bias[c0]   + r0;
                v[2*i2+1] = Cs[rloc*264 + c0+1] + bias[c0+1] + r1;
                s += v[2*i2] + v[2*i2+1];
            }
            #pragma unroll
            for (int o=16;o>0;o>>=1) s += __shfl_xor_sync(0xffffffffu, s, o);
            float mean = s * (1.f/256.f);
            float q = 0.f;
            #pragma unroll
            for (int i2=0;i2<8;i2++){ float dd = v[i2]-mean; q = fmaf(dd, dd, q); }
            #pragma unroll
            for (int o=16;o>0;o>>=1) q += __shfl_xor_sync(0xffffffffu, q, o);
            float rstd = rsqrtf(q*(1.f/256.f) + 1e-5f);
            #pragma unroll
            for (int i2=0;i2<4;i2++){
                int c0 = 2*lane + 64*i2;
                float o0 = (v[2*i2]  -mean)*rstd*g[c0]   + bta[c0];
                float o1 = (v[2*i2+1]-mean)*rstd*g[c0+1] + bta[c0+1];
                *(unsigned*)&d_Xb[(size_t)tok*DMODEL + c0] = pkbf2(o0, o1);
            }
        }
        __syncthreads();
    }
}

// ---------------- flash attention: 128 q rows, 3-stage K/V, lastOnly mode ----------------
#define A_STG (128*40)
__global__ __launch_bounds__(256, 3) void attn_kernel(int qtBase, int useMax, int lastOnly)
{
    extern __shared__ __align__(16) unsigned char dynsm_a[];
    __nv_bfloat16* Qs = (__nv_bfloat16*)dynsm_a;     // 128*40
    __nv_bfloat16* Ks = Qs + A_STG;                  // [3][128*40]
    __nv_bfloat16* Vs = Ks + 3*A_STG;                // [3][128*40]

    const int tid = threadIdx.x, lane = tid & 31, w = tid >> 5;
    const int qt = qtBase - blockIdx.x;              // heavy tiles first
    const int bh = blockIdx.y, b = bh >> 3, h = bh & 7;
    const int g = lane >> 2, tig = lane & 3;
    const int r8 = lane & 7, sel = lane >> 3;
    const int rwBase = qt*128 + w*16;
    const bool skipW = lastOnly && (w != 7);         // only warp 7's rows (incl. token 2047) matter

    auto issueKV = [&](int kt, int st){
        const __nv_bfloat16* Kg = d_QKVb + ((size_t)(b*SEQ + kt*128))*768 + 256 + h*32;
        #pragma unroll
        for (int cc = tid; cc < 512; cc += 256){
            int r = cc >> 2, off = (cc & 3)*8;
            CPA(smem_u32(&Ks[st*A_STG + r*40+off]), Kg + (size_t)r*768 + off);
            CPA(smem_u32(&Vs[st*A_STG + r*40+off]), Kg + 256 + (size_t)r*768 + off);
        }
    };

    {
        const __nv_bfloat16* Qg = d_QKVb + ((size_t)(b*SEQ + qt*128))*768 + h*32;
        #pragma unroll
        for (int cc = tid; cc < 512; cc += 256){
            int r = cc >> 2, off = (cc & 3)*8;
            CPA(smem_u32(&Qs[r*40+off]), Qg + (size_t)r*768 + off);
        }
        issueKV(0, 0); CPC();
        if (qt >= 1){ issueKV(1, 1); CPC(); }
    }

    unsigned aq[2][4];
    float o[4][4];
    #pragma unroll
    for (int j=0;j<4;j++){ o[j][0]=0.f;o[j][1]=0.f;o[j][2]=0.f;o[j][3]=0.f; }
    float l0a = 0.f, l0b = 0.f, l1a = 0.f, l1b = 0.f;   // dual accumulators (t-parity)
    float m0v = -1e30f, m1v = -1e30f;
    const int gr0 = rwBase + g;

    int cur = 0;
    for (int kt = 0; kt <= qt; kt++){
        if (kt < qt) CPW1(); else CPW0();
        __syncthreads();
        if (kt == 0 && !skipW){
            int row = w*16 + (sel & 1)*8 + r8;
            #pragma unroll
            for (int t=0;t<2;t++){
                unsigned addr = smem_u32(&Qs[row*40 + t*16 + (sel>>1)*8]);
                LDSM4(aq[t][0], aq[t][1], aq[t][2], aq[t][3], addr);
            }
        }
        if (kt+2 <= qt){
            int st = cur+2; if (st>=3) st-=3;
            issueKV(kt+2, st); CPC();
        }

        const __nv_bfloat16* Kb = Ks + cur*A_STG;
        const __nv_bfloat16* Vb = Vs + cur*A_STG;

        if (!skipW){
        #pragma unroll
        for (int h2 = 0; h2 < 2; h2++){
            const int cb = kt*128 + h2*64;
            if (cb > rwBase + 15) break;

            float s[8][4];
            #pragma unroll
            for (int j=0;j<8;j++){
                s[j][0]=0.f;s[j][1]=0.f;s[j][2]=0.f;s[j][3]=0.f;
                unsigned k0,k1,k2,k3;
                unsigned addr = smem_u32(&Kb[(h2*64 + j*8 + r8)*40 + sel*8]);
                LDSM4(k0,k1,k2,k3, addr);
                MMA16816(s[j][0],s[j][1],s[j][2],s[j][3],
                         aq[0][0],aq[0][1],aq[0][2],aq[0][3], k0,k1);
                MMA16816(s[j][0],s[j][1],s[j][2],s[j][3],
                         aq[1][0],aq[1][1],aq[1][2],aq[1][3], k2,k3);
            }

            const bool diag = (cb + 63 > rwBase);
            if (diag){
                #pragma unroll
                for (int j=0;j<8;j++){
                    int c0 = cb + j*8 + 2*tig;
                    if (c0   > gr0)   s[j][0] = -1e30f;
                    if (c0+1 > gr0)   s[j][1] = -1e30f;
                    if (c0   > gr0+8) s[j][2] = -1e30f;
                    if (c0+1 > gr0+8) s[j][3] = -1e30f;
                }
            }

            float base0 = EXP_B0, base1 = EXP_B0;
            if (useMax){
                float mt0 = -1e30f, mt1 = -1e30f;
                #pragma unroll
                for (int j=0;j<8;j++){
                    mt0 = fmaxf(mt0, fmaxf(s[j][0], s[j][1]));
                    mt1 = fmaxf(mt1, fmaxf(s[j][2], s[j][3]));
                }
                mt0 = fmaxf(mt0, __shfl_xor_sync(0xffffffffu, mt0, 1));
                mt0 = fmaxf(mt0, __shfl_xor_sync(0xffffffffu, mt0, 2));
                mt1 = fmaxf(mt1, __shfl_xor_sync(0xffffffffu, mt1, 1));
                mt1 = fmaxf(mt1, __shfl_xor_sync(0xffffffffu, mt1, 2));
                float nm0 = fmaxf(m0v, mt0), nm1 = fmaxf(m1v, mt1);
                base0 = EXP_B0 - EXP_SA*nm0;
                base1 = EXP_B0 - EXP_SA*nm1;
                float corr0 = cexpb(m0v, base0), corr1 = cexpb(m1v, base1);
                m0v = nm0; m1v = nm1;
                l0a *= corr0; l0b *= corr0;
                l1a *= corr1; l1b *= corr1;
                #pragma unroll
                for (int j=0;j<4;j++){
                    o[j][0] *= corr0; o[j][1] *= corr0;
                    o[j][2] *= corr1; o[j][3] *= corr1;
                }
            }

            const bool clampP = useMax || diag;
            unsigned pp[4][4];
            #pragma unroll
            for (int t=0;t<4;t++){
                float t00 = fmaf(s[2*t][0],   EXP_SA, base0), t01 = fmaf(s[2*t][1],   EXP_SA, base0);
                float t02 = fmaf(s[2*t][2],   EXP_SA, base1), t03 = fmaf(s[2*t][3],   EXP_SA, base1);
                float t10 = fmaf(s[2*t+1][0], EXP_SA, base0), t11 = fmaf(s[2*t+1][1], EXP_SA, base0);
                float t12 = fmaf(s[2*t+1][2], EXP_SA, base1), t13 = fmaf(s[2*t+1][3], EXP_SA, base1);
                if (clampP){
                    t00 = fmaxf(t00,0.f); t01 = fmaxf(t01,0.f);
                    t02 = fmaxf(t02,0.f); t03 = fmaxf(t03,0.f);
                    t10 = fmaxf(t10,0.f); t11 = fmaxf(t11,0.f);
                    t12 = fmaxf(t12,0.f); t13 = fmaxf(t13,0.f);
                }
                int i00 = (int)t00, i01 = (int)t01, i02 = (int)t02, i03 = (int)t03;
                int i10 = (int)t10, i11 = (int)t11, i12 = (int)t12, i13 = (int)t13;
                if (t & 1){
                    l0a += __int_as_float(i00) + __int_as_float(i01)
                         + __int_as_float(i10) + __int_as_float(i11);
                    l1a += __int_as_float(i02) + __int_as_float(i03)
                         + __int_as_float(i12) + __int_as_float(i13);
                } else {
                    l0b += __int_as_float(i00) + __int_as_float(i01)
                         + __int_as_float(i10) + __int_as_float(i11);
                    l1b += __int_as_float(i02) + __int_as_float(i03)
                         + __int_as_float(i12) + __int_as_float(i13);
                }
                pp[t][0] = prmt_hi((unsigned)i00, (unsigned)i01);
                pp[t][1] = prmt_hi((unsigned)i02, (unsigned)i03);
                pp[t][2] = prmt_hi((unsigned)i10, (unsigned)i11);
                pp[t][3] = prmt_hi((unsigned)i12, (unsigned)i13);
            }

            #pragma unroll
            for (int t=0;t<4;t++){
                unsigned v0,v1,v2,v3, x0,x1,x2,x3;
                int vrow = h2*64 + 16*t + (sel & 1)*8 + r8;
                unsigned addrA = smem_u32(&Vb[vrow*40 + (sel>>1)*8]);
                unsigned addrB = smem_u32(&Vb[vrow*40 + 16 + (sel>>1)*8]);
                LDSM4T(v0,v1,v2,v3, addrA);
                LDSM4T(x0,x1,x2,x3, addrB);
                MMA16816(o[0][0],o[0][1],o[0][2],o[0][3], pp[t][0],pp[t][1],pp[t][2],pp[t][3], v0,v1);
                MMA16816(o[1][0],o[1][1],o[1][2],o[1][3], pp[t][0],pp[t][1],pp[t][2],pp[t][3], v2,v3);
                MMA16816(o[2][0],o[2][1],o[2][2],o[2][3], pp[t][0],pp[t][1],pp[t][2],pp[t][3], x0,x1);
                MMA16816(o[3][0],o[3][1],o[3][2],o[3][3], pp[t][0],pp[t][1],pp[t][2],pp[t][3], x2,x3);
            }
        }
        }   // !skipW
        cur = (cur+1 == 3) ? 0 : cur+1;
    }

    if (!skipW){
        float l0 = l0a + l0b, l1 = l1a + l1b;
        l0 += __shfl_xor_sync(0xffffffffu, l0, 1);
        l0 += __shfl_xor_sync(0xffffffffu, l0, 2);
        l1 += __shfl_xor_sync(0xffffffffu, l1, 1);
        l1 += __shfl_xor_sync(0xffffffffu, l1, 2);
        float rl0 = __fdividef(1.f, l0), rl1 = __fdividef(1.f, l1);
        __nv_bfloat16* Og0 = d_ATTb + ((size_t)(b*SEQ + rwBase + g))*256 + h*32;
        __nv_bfloat16* Og1 = Og0 + (size_t)8*256;
        #pragma unroll
        for (int j=0;j<4;j++){
            int dcol = j*8 + 2*tig;
            *(unsigned*)&Og0[dcol] = pkbf2(o[j][0]*rl0, o[j][1]*rl0);
            *(unsigned*)&Og1[dcol] = pkbf2(o[j][2]*rl1, o[j][3]*rl1);
        }
    }
}

// ---------------- dec + hist + IDM + fusion ----------------
__global__ void final_kernel(const float* __restrict__ inputs,
    const float* __restrict__ his,
    const float* __restrict__ W_dec, const float* __restrict__ b_dec,
    const float* __restrict__ W_fus, const float* __restrict__ b_fus,
    float* __restrict__ out)
{
    __shared__ float dec[8], yidm[8][LOUT], lastpos[8], dvb[8];
    int tid = threadIdx.x, wid = tid>>5, lane = tid&31;
    {
        const __nv_bfloat16* row = d_Xb + ((size_t)(wid*SEQ + SEQ-1))*DMODEL;
        float s = 0.f;
        #pragma unroll
        for (int i=0;i<8;i++){
            int d_ = lane + i*32;
            s = fmaf(__bfloat162float(row[d_]), W_dec[d_], s);
        }
        #pragma unroll
        for (int o=16;o>0;o>>=1) s += __shfl_xor_sync(0xffffffffu, s, o);
        if (lane==0) dec[wid] = s + b_dec[0];
    }
    if (tid < 8){
        int b = tid;
        float lp = inputs[((size_t)(b*SEQ + SEQ-1))*4];
        lastpos[b] = lp;
        dvb[b] = (lp - inputs[((size_t)(b*SEQ + SEQ-1-LOUT))*4]) / 50.f;
    }
    __syncthreads();

    if (tid < 8){
        int b = tid;
        const float* il = inputs + ((size_t)(b*SEQ + SEQ-1))*4;
        float y = il[0], v = il[1], sg = il[2], dv = il[3];
        const float sqab2 = 2.449489742783178f;
        float sx = 2.0f + fmaxf(0.f, v*1.5f + v*dv/sqab2);
        float t = v/30.0f; float p = t*t; p *= p;
        float rr = sx/sg;
        float af = (1.f - p - rr*rr);
        float v0 = fmaxf(v + af*0.1f, 0.f);
        float v0last = __shfl_sync(0xffu, v0, 7);   // reference's v0[-1] broadcast
        float yp = y + v0last*0.1f;
        float vp = v0;
        yidm[b][0] = yp;
        for (int j=0;j<LOUT-1;j++){
            float hp = his[((size_t)(b*LOUT + j))*2];
            float hv = his[((size_t)(b*LOUT + j))*2 + 1];
            float dvj = hv - vp;
            float sj  = hp - yp;
            float sxj = 2.0f + fmaxf(0.f, vp*1.5f + vp*dvj/sqab2);
            float tt = vp/30.0f; float q4 = tt*tt; q4 *= q4;
            float r2 = sxj/sj;
            float acc = (1.f - q4 - r2*r2);
            float v2 = vp + acc*0.1f;
            v2 = (v2 <= 0.f) ? 0.f : v2;
            yp = yp + v2*0.1f;
            yidm[b][j+1] = yp;
            vp = v2;
        }
    }
    __syncthreads();

    float w0 = W_fus[0], w1 = W_fus[1], w2 = W_fus[2], bb = b_fus[0];
    for (int t = tid; t < BATCH*LOUT; t += 256){
        int b = t / LOUT, l = t % LOUT;
        out[t] = w0*dec[b] + w1*(lastpos[b] + dvb[b]*(float)(l+1)) + w2*yidm[b][l] + bb;
    }
}

// ---------------- launcher ----------------
#define GLN_SMEM    76800
#define ATT_SMEM    71680

extern "C" void kernel_launch(void* const* d_in, const int* in_sizes, int n_in,
                              void* d_out, int out_size)
{
    (void)in_sizes; (void)n_in; (void)out_size;
    const float* inputs = (const float*)d_in[0];
    const float* his    = (const float*)d_in[1];
    const float* W_emb  = (const float*)d_in[2];
    const float* b_emb  = (const float*)d_in[3];
    const float* Wqkv   = (const float*)d_in[4];
    const float* bqkv   = (const float*)d_in[5];
    const float* Wo     = (const float*)d_in[6];
    const float* bo     = (const float*)d_in[7];
    const float* W1     = (const float*)d_in[8];
    const float* b1     = (const float*)d_in[9];
    const float* W2     = (const float*)d_in[10];
    const float* b2     = (const float*)d_in[11];
    const float* ln1g   = (const float*)d_in[12];
    const float* ln1b   = (const float*)d_in[13];
    const float* ln2g   = (const float*)d_in[14];
    const float* ln2b   = (const float*)d_in[15];
    const float* W_dec  = (const float*)d_in[16];
    const float* b_dec  = (const float*)d_in[17];
    const float* W_fus  = (const float*)d_in[18];
    const float* b_fus  = (const float*)d_in[19];
    float* out = (float*)d_out;

    cudaFuncSetAttribute(gemm_kernel,    cudaFuncAttributeMaxDynamicSharedMemorySize, GEMM_SMEM);
    cudaFuncSetAttribute(gemm_ln_kernel, cudaFuncAttributeMaxDynamicSharedMemorySize, GLN_SMEM);
    cudaFuncSetAttribute(attn_kernel,    cudaFuncAttributeMaxDynamicSharedMemorySize, ATT_SMEM);

    void *pXb_, *pHb_, *pWq_, *pWo_, *pW1_, *pW2_, *pATT_, *pQKV_;
    cudaGetSymbolAddress(&pXb_,  d_Xb);
    cudaGetSymbolAddress(&pHb_,  d_Hb);
    cudaGetSymbolAddress(&pWq_,  d_WqkvB);
    cudaGetSymbolAddress(&pWo_,  d_WoB);
    cudaGetSymbolAddress(&pW1_,  d_W1B);
    cudaGetSymbolAddress(&pW2_,  d_W2B);
    cudaGetSymbolAddress(&pATT_, d_ATTb);
    cudaGetSymbolAddress(&pQKV_, d_QKVb);

    __nv_bfloat16* Xb   = (__nv_bfloat16*)pXb_;
    __nv_bfloat16* Hb   = (__nv_bfloat16*)pHb_;
    __nv_bfloat16* WqB  = (__nv_bfloat16*)pWq_;
    __nv_bfloat16* WoB  = (__nv_bfloat16*)pWo_;
    __nv_bfloat16* W1B  = (__nv_bfloat16*)pW1_;
    __nv_bfloat16* W2B  = (__nv_bfloat16*)pW2_;
    __nv_bfloat16* ATTb = (__nv_bfloat16*)pATT_;
    __nv_bfloat16* QKVb = (__nv_bfloat16*)pQKV_;

    conv4_kernel<<<(N0+N1+N2+N3)/4/256, 256>>>(Wqkv, Wo, W1, W2);
    prep0_kernel<<<1, 256>>>(Wqkv, bqkv, W_emb, b_emb);
    embed0_kernel<<<NTOK, 128>>>(inputs, W_emb, b_emb);

    for (int l = 0; l < NLAY; l++){
        int sp = (l == NLAY-1);
        int useMax = (l == 0);

        if (l > 0){
            if (!sp){
                gemm_kernel<<<dim3(6,128), 256, GEMM_SMEM>>>(Xb, WqB + (size_t)l*768*256,
                    bqkv + l*768, QKVb, 768, 256, 0, 1, 0, 0);
            } else {
                gemm_kernel<<<dim3(4,128), 256, GEMM_SMEM>>>(Xb, WqB + (size_t)l*768*256,
                    bqkv + l*768, QKVb, 768, 256, 0, 1, 0, 256);
                gemm_kernel<<<dim3(2,8), 256, GEMM_SMEM>>>(Xb, WqB + (size_t)l*768*256,
                    bqkv + l*768, QKVb, 768, 256, 0, 16, 15, 0);
            }
        }

        if (!sp) attn_kernel<<<dim3(16,64), 256, ATT_SMEM>>>(15, useMax, 0);
        else     attn_kernel<<<dim3(1,64),  256, ATT_SMEM>>>(15, useMax, 1);

        gemm_ln_kernel<<<dim3(1, sp?8:256), 256, GLN_SMEM>>>(ATTb, WoB + (size_t)l*256*256,
            bo + l*256, ln1g + l*256, ln1b + l*256, 256, sp);

        gemm_kernel<<<dim3(8, sp?8:128), 256, GEMM_SMEM>>>(Xb, W1B + (size_t)l*1024*256,
            b1 + l*1024, Hb, 1024, 256, 1, sp?16:1, sp?15:0, 0);

        gemm_ln_kernel<<<dim3(1, sp?8:256), 256, GLN_SMEM>>>(Hb, W2B + (size_t)l*256*1024,
            b2 + l*256, ln2g + l*256, ln2b + l*256, 1024, sp);
    }

    final_kernel<<<1, 256>>>(inputs, his, W_dec, b_dec, W_fus, b_fus, out);
}